// round 12
// baseline (speedup 1.0000x reference)
#include <cuda_runtime.h>
#include <cuda_bf16.h>
#include <cstdint>

#define DI __device__ __forceinline__

// ======================= scratch =======================
__device__ __nv_bfloat16 g_wh[192 * 1024], g_wl[192 * 1024];
__device__ __nv_bfloat16 g_kh[16384 * 64], g_kl[16384 * 64];
__device__ __nv_bfloat16 g_qh[16384 * 64], g_ql[16384 * 64];
__device__ __nv_bfloat16 g_vh[16384 * 64], g_vl[16384 * 64];
// kv-split partials
__device__ float g_op[2][16384 * 64];
__device__ float g_lp[2][16384];

// ======================= helpers =======================
DI uint32_t smem_u32(const void* p) {
    uint32_t a;
    asm("{ .reg .u64 t; cvta.to.shared.u64 t, %1; cvt.u32.u64 %0, t; }" : "=r"(a) : "l"(p));
    return a;
}
DI uint32_t sw(uint32_t o) { return o ^ ((o >> 3) & 0x70); }  // SW128 swizzle (bf16 tiles)

// fast split: hi = truncate-to-bf16 (exact residual), lo = rn(residual pair).
DI void split2(float a, float b, uint32_t& h, uint32_t& l) {
    uint32_t ua = __float_as_uint(a), ub = __float_as_uint(b);
    asm("prmt.b32 %0, %1, %2, 0x7632;" : "=r"(h) : "r"(ua), "r"(ub));
    float ra = a - __uint_as_float(ua & 0xFFFF0000u);
    float rb = b - __uint_as_float(ub & 0xFFFF0000u);
    asm("cvt.rn.bf16x2.f32 %0, %1, %2;" : "=r"(l) : "f"(rb), "f"(ra));
}

DI void mma16816(float* d, const uint32_t* a, const uint32_t* b) {
    asm volatile(
        "mma.sync.aligned.m16n8k16.row.col.f32.bf16.bf16.f32 "
        "{%0,%1,%2,%3}, {%4,%5,%6,%7}, {%8,%9}, {%0,%1,%2,%3};"
        : "+f"(d[0]), "+f"(d[1]), "+f"(d[2]), "+f"(d[3])
        : "r"(a[0]), "r"(a[1]), "r"(a[2]), "r"(a[3]), "r"(b[0]), "r"(b[1]));
}
DI void ldsm4(uint32_t* r, uint32_t addr) {
    asm volatile("ldmatrix.sync.aligned.m8n8.x4.shared.b16 {%0,%1,%2,%3}, [%4];"
                 : "=r"(r[0]), "=r"(r[1]), "=r"(r[2]), "=r"(r[3]) : "r"(addr));
}
DI void ldsm4t(uint32_t* r, uint32_t addr) {
    asm volatile("ldmatrix.sync.aligned.m8n8.x4.trans.shared.b16 {%0,%1,%2,%3}, [%4];"
                 : "=r"(r[0]), "=r"(r[1]), "=r"(r[2]), "=r"(r[3]) : "r"(addr));
}
DI void cpa(uint32_t dst, const void* src) {
    asm volatile("cp.async.cg.shared.global [%0], [%1], 16;" :: "r"(dst), "l"(src));
}
#define CP_COMMIT()  asm volatile("cp.async.commit_group;" ::: "memory")
#define CP_WAIT(n)   asm volatile("cp.async.wait_group %0;" :: "n"(n) : "memory")

// ======================= kernel 1: W split (tiny) =======================
__global__ void wsplit_kernel(const float* __restrict__ Wk,
                              const float* __restrict__ Wq,
                              const float* __restrict__ Wv) {
    const int idx = blockIdx.x * 256 + threadIdx.x;   // 49152 float4s
    int r = idx >> 8;
    const float* src = (r < 64) ? Wk : (r < 128) ? Wq : Wv;
    float sc = (r >= 64 && r < 128) ? 0.125f : 1.0f;  // fold 1/sqrt(64) into Q
    float4 f = ((const float4*)(src + (size_t)(r & 63) * 1024))[idx & 255];
    uint2 h, l;
    split2(f.x * sc, f.y * sc, h.x, l.x);
    split2(f.z * sc, f.w * sc, h.y, l.y);
    ((uint2*)g_wh)[idx] = h;
    ((uint2*)g_wl)[idx] = l;
}

// ======================= kernel 2: projection (x split fused, R11) ==========
#define PJ_BUF 57344
#define PJ_XS  0
#define PJ_WH  32768
#define PJ_WL  45056
#define PJ_SMEM (2 * PJ_BUF)

__global__ __launch_bounds__(256, 2)
void proj_kernel(const float* __restrict__ x) {
    extern __shared__ char smem[];
    const uint32_t sbase = smem_u32(smem);
    const int tid = threadIdx.x;
    const int wid = tid >> 5, lane = tid & 31;
    const int wm = wid >> 1, wn = wid & 1;
    const int g = lane >> 2, c = lane & 3;
    const int m0 = blockIdx.x * 128;
    const int n0 = blockIdx.y * 96;

    auto load_step = [&](int s, int buf) {
        const int k0 = s * 64;
        const uint32_t bb = sbase + buf * PJ_BUF;
        #pragma unroll
        for (int j = 0; j < 8; ++j) {
            int ch = tid + 256 * j;
            int row = ch >> 4, c16 = ch & 15;
            uint32_t d = (uint32_t)row * 256 +
                         ((((uint32_t)(c16 >> 1) ^ ((uint32_t)row & 7)) * 8 + (c16 & 1) * 4) * 4);
            cpa(bb + PJ_XS + d, x + (size_t)(m0 + row) * 1024 + k0 + c16 * 4);
        }
        #pragma unroll
        for (int j = 0; j < 3; ++j) {
            int ch = tid + 256 * j;
            int row = ch >> 3, col16 = ch & 7;
            uint32_t d = sw((uint32_t)row * 128 + col16 * 16);
            size_t srcoff = (size_t)(n0 + row) * 1024 + k0 + col16 * 8;
            cpa(bb + PJ_WH + d, g_wh + srcoff);
            cpa(bb + PJ_WL + d, g_wl + srcoff);
        }
    };

    float acc[2][6][4];
    #pragma unroll
    for (int t = 0; t < 2; ++t)
        #pragma unroll
        for (int j = 0; j < 6; ++j)
            #pragma unroll
            for (int q = 0; q < 4; ++q) acc[t][j][q] = 0.0f;

    load_step(0, 0);
    CP_COMMIT();

    const uint32_t brow_in = (uint32_t)(((lane >> 4) & 1) * 8 + (lane & 7));
    const uint32_t bcolsel = ((lane >> 3) & 1) * 16;
    const uint32_t arow_lo = (uint32_t)(wm * 32 + (lane >> 2));
    const uint32_t acol_in = (uint32_t)((lane & 3) * 2);

    for (int s = 0; s < 16; ++s) {
        const int buf = s & 1;
        if (s < 15) { load_step(s + 1, buf ^ 1); CP_COMMIT(); CP_WAIT(1); }
        else        { CP_WAIT(0); }
        __syncthreads();

        const uint32_t bb = sbase + buf * PJ_BUF;
        const char* XS = smem + buf * PJ_BUF + PJ_XS;

        #pragma unroll
        for (int kb = 0; kb < 4; ++kb) {
            uint32_t ah[2][4], al[2][4];
            #pragma unroll
            for (int t = 0; t < 2; ++t) {
                const uint32_t r = arow_lo + t * 16;
                const uint32_t x7 = r & 7;
                const uint32_t rb0 = r * 256, rb8 = (r + 8) * 256;
                const uint32_t g0 = (((uint32_t)(kb * 2)     ^ x7) * 8 + acol_in) * 4;
                const uint32_t g1 = (((uint32_t)(kb * 2 + 1) ^ x7) * 8 + acol_in) * 4;
                float2 p0 = *(const float2*)(XS + rb0 + g0);
                float2 p1 = *(const float2*)(XS + rb8 + g0);
                float2 p2 = *(const float2*)(XS + rb0 + g1);
                float2 p3 = *(const float2*)(XS + rb8 + g1);
                split2(p0.x, p0.y, ah[t][0], al[t][0]);
                split2(p1.x, p1.y, ah[t][1], al[t][1]);
                split2(p2.x, p2.y, ah[t][2], al[t][2]);
                split2(p3.x, p3.y, ah[t][3], al[t][3]);
            }
            #pragma unroll
            for (int nb2 = 0; nb2 < 3; ++nb2) {
                uint32_t bh[4], bl[4];
                uint32_t row = (uint32_t)(wn * 48 + nb2 * 16) + brow_in;
                uint32_t off = sw(row * 128 + kb * 32 + bcolsel);
                ldsm4(bh, bb + PJ_WH + off);
                ldsm4(bl, bb + PJ_WL + off);
                #pragma unroll
                for (int t = 0; t < 2; ++t) {
                    mma16816(acc[t][2 * nb2],     ah[t], bh);
                    mma16816(acc[t][2 * nb2],     ah[t], bl);
                    mma16816(acc[t][2 * nb2],     al[t], bh);
                    mma16816(acc[t][2 * nb2 + 1], ah[t], bh + 2);
                    mma16816(acc[t][2 * nb2 + 1], ah[t], bl + 2);
                    mma16816(acc[t][2 * nb2 + 1], al[t], bh + 2);
                }
            }
        }
        __syncthreads();
    }

    uint32_t* kh32 = (uint32_t*)g_kh; uint32_t* kl32 = (uint32_t*)g_kl;
    uint32_t* qh32 = (uint32_t*)g_qh; uint32_t* ql32 = (uint32_t*)g_ql;
    uint32_t* vh32 = (uint32_t*)g_vh; uint32_t* vl32 = (uint32_t*)g_vl;
    #pragma unroll
    for (int t = 0; t < 2; ++t) {
        const int r0 = m0 + wm * 32 + t * 16 + g;
        #pragma unroll
        for (int j = 0; j < 6; ++j) {
            const int ncol = n0 + wn * 48 + j * 8 + 2 * c;
            uint32_t h0, l0, h1, l1;
            split2(acc[t][j][0], acc[t][j][1], h0, l0);
            split2(acc[t][j][2], acc[t][j][3], h1, l1);
            uint32_t *dh, *dl;
            int c2;
            if (ncol < 64)       { dh = kh32; dl = kl32; c2 = ncol >> 1; }
            else if (ncol < 128) { dh = qh32; dl = ql32; c2 = (ncol - 64) >> 1; }
            else                 { dh = vh32; dl = vl32; c2 = (ncol - 128) >> 1; }
            dh[(size_t)r0 * 32 + c2] = h0;       dl[(size_t)r0 * 32 + c2] = l0;
            dh[(size_t)(r0 + 8) * 32 + c2] = h1; dl[(size_t)(r0 + 8) * 32 + c2] = l1;
        }
    }
}

// ======================= kernel 3: attention (kv-split x2, 3 CTA/SM) ========
// CTA: 64 queries (4 warps x 16 rows), keys: half range per blockIdx.z.
// Q-lo lives in smem (ldsm per kb) to cut registers; Q-hi stays in regs.
// smem: QL 8K + 2 x 32K KV stages = 72K -> 3 CTA/SM (216K), 12 warps/SM.
#define AT_QL   0
#define AT_ST0  8192
#define AT_STAGE 32768
#define AT_KH  0
#define AT_KL  8192
#define AT_VH  16384
#define AT_VL  24576
#define AT_SMEM (AT_ST0 + 2 * AT_STAGE)

__global__ __launch_bounds__(128, 3)
void attn_kernel() {
    extern __shared__ char smem[];
    const uint32_t sbase = smem_u32(smem);
    const int tid = threadIdx.x;
    const int wid = tid >> 5, lane = tid & 31;
    const int g = lane >> 2, c = lane & 3;
    const int b = blockIdx.y;
    const int q0 = blockIdx.x * 64;
    const int z = blockIdx.z;
    const int kk0 = z * 1024;

    // ---- Q-hi fragments in registers; Q-lo staged to smem ----
    uint32_t qh[4][4];
    {
        const uint32_t* qh32 = (const uint32_t*)g_qh;
        const size_t r0 = (size_t)(b * 2048 + q0 + wid * 16 + g) * 32;
        const size_t r1 = r0 + 8 * 32;
        #pragma unroll
        for (int kb = 0; kb < 4; ++kb) {
            const int c0 = kb * 8 + c;
            qh[kb][0] = qh32[r0 + c0];     qh[kb][1] = qh32[r1 + c0];
            qh[kb][2] = qh32[r0 + c0 + 4]; qh[kb][3] = qh32[r1 + c0 + 4];
        }
    }
    // Q-lo: 64 rows x 128B, SW128, via cp.async (512 chunks / 128 thr = 4 each)
    {
        #pragma unroll
        for (int j = 0; j < 4; ++j) {
            int ch = tid + 128 * j;
            int row = ch >> 3, col16 = ch & 7;
            uint32_t d = sw((uint32_t)row * 128 + col16 * 16);
            cpa(sbase + AT_QL + d, g_ql + (size_t)(b * 2048 + q0 + row) * 64 + col16 * 8);
        }
    }

    auto load_kv = [&](int kt, int buf) {
        const uint32_t bb = sbase + AT_ST0 + buf * AT_STAGE;
        #pragma unroll
        for (int j = 0; j < 4; ++j) {
            int ch = tid + 128 * j;
            int row = ch >> 3, col16 = ch & 7;
            uint32_t d = sw((uint32_t)row * 128 + col16 * 16);
            size_t srcoff = (size_t)(b * 2048 + kk0 + kt * 64 + row) * 64 + col16 * 8;
            cpa(bb + AT_KH + d, g_kh + srcoff);
            cpa(bb + AT_KL + d, g_kl + srcoff);
            cpa(bb + AT_VH + d, g_vh + srcoff);
            cpa(bb + AT_VL + d, g_vl + srcoff);
        }
    };

    float o[8][4];
    #pragma unroll
    for (int f = 0; f < 8; ++f)
        #pragma unroll
        for (int q = 0; q < 4; ++q) o[f][q] = 0.0f;
    float l0 = 0.0f, l1 = 0.0f;

    load_kv(0, 0);   // same commit group as Q-lo
    CP_COMMIT();

    const uint32_t kb_row_in = (uint32_t)(((lane >> 4) & 1) * 8 + (lane & 7));
    const uint32_t kb_colsel = ((lane >> 3) & 1) * 16;
    const uint32_t vb_row_in = (uint32_t)(((lane >> 3) & 1) * 8 + (lane & 7));
    const uint32_t qa_row = (uint32_t)(wid * 16 + (lane & 15));
    const uint32_t qa_colsel = ((lane >> 4) & 1) * 16;

    for (int kt = 0; kt < 16; ++kt) {
        const int buf = kt & 1;
        if (kt < 15) { load_kv(kt + 1, buf ^ 1); CP_COMMIT(); CP_WAIT(1); }
        else         { CP_WAIT(0); }
        __syncthreads();
        const uint32_t bb = sbase + AT_ST0 + buf * AT_STAGE;

        // ---- S = Q K^T (3-term; Q-lo frag ldsm'd from smem per kb) ----
        float s[8][4];
        #pragma unroll
        for (int f = 0; f < 8; ++f)
            #pragma unroll
            for (int q = 0; q < 4; ++q) s[f][q] = 0.0f;

        #pragma unroll
        for (int kb = 0; kb < 4; ++kb) {
            uint32_t qlf[4];
            ldsm4(qlf, sbase + AT_QL + sw(qa_row * 128 + kb * 32 + qa_colsel));
            #pragma unroll
            for (int nb2 = 0; nb2 < 4; ++nb2) {
                uint32_t bh[4], bl[4];
                uint32_t row = (uint32_t)(nb2 * 16) + kb_row_in;
                uint32_t off = sw(row * 128 + kb * 32 + kb_colsel);
                ldsm4(bh, bb + AT_KH + off);
                ldsm4(bl, bb + AT_KL + off);
                mma16816(s[2 * nb2],     qh[kb], bh);
                mma16816(s[2 * nb2],     qh[kb], bl);
                mma16816(s[2 * nb2],     qlf,    bh);
                mma16816(s[2 * nb2 + 1], qh[kb], bh + 2);
                mma16816(s[2 * nb2 + 1], qh[kb], bl + 2);
                mma16816(s[2 * nb2 + 1], qlf,    bh + 2);
            }
        }

        // ---- softmax (no max subtraction: logits bounded) ----
        uint32_t ph[16], pl[16];
        #pragma unroll
        for (int f = 0; f < 8; ++f) {
            float p0 = __expf(s[f][0]), p1 = __expf(s[f][1]);
            float p2 = __expf(s[f][2]), p3 = __expf(s[f][3]);
            l0 += p0 + p1;
            l1 += p2 + p3;
            split2(p0, p1, ph[2 * f], pl[2 * f]);
            split2(p2, p3, ph[2 * f + 1], pl[2 * f + 1]);
        }

        // ---- O += P V (3-term) ----
        #pragma unroll
        for (int kb = 0; kb < 4; ++kb) {
            const uint32_t* pa = ph + 4 * kb;
            const uint32_t* pb = pl + 4 * kb;
            #pragma unroll
            for (int nb2 = 0; nb2 < 4; ++nb2) {
                uint32_t vhf[4], vlf[4];
                uint32_t row = (uint32_t)(kb * 16) + vb_row_in;
                uint32_t off = sw(row * 128 + (2 * nb2 + (lane >> 4)) * 16);
                ldsm4t(vhf, bb + AT_VH + off);
                ldsm4t(vlf, bb + AT_VL + off);
                mma16816(o[2 * nb2],     pa, vhf);
                mma16816(o[2 * nb2],     pa, vlf);
                mma16816(o[2 * nb2],     pb, vhf);
                mma16816(o[2 * nb2 + 1], pa, vhf + 2);
                mma16816(o[2 * nb2 + 1], pa, vlf + 2);
                mma16816(o[2 * nb2 + 1], pb, vhf + 2);
            }
        }
        __syncthreads();
    }

    // ---- quad-reduce l, write unnormalized partials ----
    l0 += __shfl_xor_sync(0xffffffffu, l0, 1);
    l0 += __shfl_xor_sync(0xffffffffu, l0, 2);
    l1 += __shfl_xor_sync(0xffffffffu, l1, 1);
    l1 += __shfl_xor_sync(0xffffffffu, l1, 2);

    float* op = g_op[z];
    const int r0 = b * 2048 + q0 + wid * 16 + g;
    #pragma unroll
    for (int f = 0; f < 8; ++f) {
        const int col = f * 8 + 2 * c;
        *(float2*)(op + (size_t)r0 * 64 + col)       = make_float2(o[f][0], o[f][1]);
        *(float2*)(op + (size_t)(r0 + 8) * 64 + col) = make_float2(o[f][2], o[f][3]);
    }
    if (c == 0) {
        g_lp[z][r0]     = l0;
        g_lp[z][r0 + 8] = l1;
    }
}

// ======================= kernel 4: kv-split reduce =======================
__global__ void reduce_kernel(float* __restrict__ out) {
    const int idx = blockIdx.x * 256 + threadIdx.x;   // float4 index, 262144 total
    const int row = idx >> 4;
    const float inv = 1.0f / (g_lp[0][row] + g_lp[1][row]);
    float4 a = ((const float4*)g_op[0])[idx];
    float4 bq = ((const float4*)g_op[1])[idx];
    float4 r;
    r.x = (a.x + bq.x) * inv;
    r.y = (a.y + bq.y) * inv;
    r.z = (a.z + bq.z) * inv;
    r.w = (a.w + bq.w) * inv;
    ((float4*)out)[idx] = r;
}

// ======================= launch =======================
extern "C" void kernel_launch(void* const* d_in, const int* in_sizes, int n_in,
                              void* d_out, int out_size) {
    const float* x  = (const float*)d_in[0];
    const float* Wk = (const float*)d_in[1];
    const float* Wq = (const float*)d_in[2];
    const float* Wv = (const float*)d_in[3];
    float* out = (float*)d_out;

    cudaFuncSetAttribute(proj_kernel, cudaFuncAttributeMaxDynamicSharedMemorySize, PJ_SMEM);
    cudaFuncSetAttribute(attn_kernel, cudaFuncAttributeMaxDynamicSharedMemorySize, AT_SMEM);

    wsplit_kernel<<<192, 256>>>(Wk, Wq, Wv);
    proj_kernel<<<dim3(128, 2), 256, PJ_SMEM>>>(x);
    attn_kernel<<<dim3(32, 8, 2), 128, AT_SMEM>>>();
    reduce_kernel<<<1024, 256>>>(out);
}

// round 13
// speedup vs baseline: 1.0620x; 1.0620x over previous
#include <cuda_runtime.h>
#include <cuda_bf16.h>
#include <cstdint>

#define DI __device__ __forceinline__

// ======================= scratch =======================
__device__ __nv_bfloat16 g_wh[192 * 1024], g_wl[192 * 1024];
__device__ __nv_bfloat16 g_kh[16384 * 64], g_kl[16384 * 64];
__device__ __nv_bfloat16 g_qh[16384 * 64], g_ql[16384 * 64];
__device__ __nv_bfloat16 g_vh[16384 * 64], g_vl[16384 * 64];

// ======================= helpers =======================
DI uint32_t smem_u32(const void* p) {
    uint32_t a;
    asm("{ .reg .u64 t; cvta.to.shared.u64 t, %1; cvt.u32.u64 %0, t; }" : "=r"(a) : "l"(p));
    return a;
}
DI uint32_t sw(uint32_t o) { return o ^ ((o >> 3) & 0x70); }  // SW128 swizzle (bf16 tiles)

// fast split: hi = truncate-to-bf16 (exact residual), lo = rn(residual pair).
DI void split2(float a, float b, uint32_t& h, uint32_t& l) {
    uint32_t ua = __float_as_uint(a), ub = __float_as_uint(b);
    asm("prmt.b32 %0, %1, %2, 0x7632;" : "=r"(h) : "r"(ua), "r"(ub));
    float ra = a - __uint_as_float(ua & 0xFFFF0000u);
    float rb = b - __uint_as_float(ub & 0xFFFF0000u);
    asm("cvt.rn.bf16x2.f32 %0, %1, %2;" : "=r"(l) : "f"(rb), "f"(ra));
}

DI void mma16816(float* d, const uint32_t* a, const uint32_t* b) {
    asm volatile(
        "mma.sync.aligned.m16n8k16.row.col.f32.bf16.bf16.f32 "
        "{%0,%1,%2,%3}, {%4,%5,%6,%7}, {%8,%9}, {%0,%1,%2,%3};"
        : "+f"(d[0]), "+f"(d[1]), "+f"(d[2]), "+f"(d[3])
        : "r"(a[0]), "r"(a[1]), "r"(a[2]), "r"(a[3]), "r"(b[0]), "r"(b[1]));
}
DI void ldsm4(uint32_t* r, uint32_t addr) {
    asm volatile("ldmatrix.sync.aligned.m8n8.x4.shared.b16 {%0,%1,%2,%3}, [%4];"
                 : "=r"(r[0]), "=r"(r[1]), "=r"(r[2]), "=r"(r[3]) : "r"(addr));
}
DI void ldsm4t(uint32_t* r, uint32_t addr) {
    asm volatile("ldmatrix.sync.aligned.m8n8.x4.trans.shared.b16 {%0,%1,%2,%3}, [%4];"
                 : "=r"(r[0]), "=r"(r[1]), "=r"(r[2]), "=r"(r[3]) : "r"(addr));
}
DI void cpa(uint32_t dst, const void* src) {
    asm volatile("cp.async.cg.shared.global [%0], [%1], 16;" :: "r"(dst), "l"(src));
}
#define CP_COMMIT()  asm volatile("cp.async.commit_group;" ::: "memory")
#define CP_WAIT(n)   asm volatile("cp.async.wait_group %0;" :: "n"(n) : "memory")

// ======================= kernel 1: W split (tiny) =======================
__global__ void wsplit_kernel(const float* __restrict__ Wk,
                              const float* __restrict__ Wq,
                              const float* __restrict__ Wv) {
    const int idx = blockIdx.x * 256 + threadIdx.x;   // 49152 float4s
    int r = idx >> 8;
    const float* src = (r < 64) ? Wk : (r < 128) ? Wq : Wv;
    float sc = (r >= 64 && r < 128) ? 0.125f : 1.0f;  // fold 1/sqrt(64) into Q
    float4 f = ((const float4*)(src + (size_t)(r & 63) * 1024))[idx & 255];
    uint2 h, l;
    split2(f.x * sc, f.y * sc, h.x, l.x);
    split2(f.z * sc, f.w * sc, h.y, l.y);
    ((uint2*)g_wh)[idx] = h;
    ((uint2*)g_wl)[idx] = l;
}

// ======================= kernel 2: projection (x split fused, R11) ==========
#define PJ_BUF 57344
#define PJ_XS  0
#define PJ_WH  32768
#define PJ_WL  45056
#define PJ_SMEM (2 * PJ_BUF)

__global__ __launch_bounds__(256, 2)
void proj_kernel(const float* __restrict__ x) {
    extern __shared__ char smem[];
    const uint32_t sbase = smem_u32(smem);
    const int tid = threadIdx.x;
    const int wid = tid >> 5, lane = tid & 31;
    const int wm = wid >> 1, wn = wid & 1;
    const int g = lane >> 2, c = lane & 3;
    const int m0 = blockIdx.x * 128;
    const int n0 = blockIdx.y * 96;

    auto load_step = [&](int s, int buf) {
        const int k0 = s * 64;
        const uint32_t bb = sbase + buf * PJ_BUF;
        #pragma unroll
        for (int j = 0; j < 8; ++j) {
            int ch = tid + 256 * j;
            int row = ch >> 4, c16 = ch & 15;
            uint32_t d = (uint32_t)row * 256 +
                         ((((uint32_t)(c16 >> 1) ^ ((uint32_t)row & 7)) * 8 + (c16 & 1) * 4) * 4);
            cpa(bb + PJ_XS + d, x + (size_t)(m0 + row) * 1024 + k0 + c16 * 4);
        }
        #pragma unroll
        for (int j = 0; j < 3; ++j) {
            int ch = tid + 256 * j;
            int row = ch >> 3, col16 = ch & 7;
            uint32_t d = sw((uint32_t)row * 128 + col16 * 16);
            size_t srcoff = (size_t)(n0 + row) * 1024 + k0 + col16 * 8;
            cpa(bb + PJ_WH + d, g_wh + srcoff);
            cpa(bb + PJ_WL + d, g_wl + srcoff);
        }
    };

    float acc[2][6][4];
    #pragma unroll
    for (int t = 0; t < 2; ++t)
        #pragma unroll
        for (int j = 0; j < 6; ++j)
            #pragma unroll
            for (int q = 0; q < 4; ++q) acc[t][j][q] = 0.0f;

    load_step(0, 0);
    CP_COMMIT();

    const uint32_t brow_in = (uint32_t)(((lane >> 4) & 1) * 8 + (lane & 7));
    const uint32_t bcolsel = ((lane >> 3) & 1) * 16;
    const uint32_t arow_lo = (uint32_t)(wm * 32 + (lane >> 2));
    const uint32_t acol_in = (uint32_t)((lane & 3) * 2);

    for (int s = 0; s < 16; ++s) {
        const int buf = s & 1;
        if (s < 15) { load_step(s + 1, buf ^ 1); CP_COMMIT(); CP_WAIT(1); }
        else        { CP_WAIT(0); }
        __syncthreads();

        const uint32_t bb = sbase + buf * PJ_BUF;
        const char* XS = smem + buf * PJ_BUF + PJ_XS;

        #pragma unroll
        for (int kb = 0; kb < 4; ++kb) {
            uint32_t ah[2][4], al[2][4];
            #pragma unroll
            for (int t = 0; t < 2; ++t) {
                const uint32_t r = arow_lo + t * 16;
                const uint32_t x7 = r & 7;
                const uint32_t rb0 = r * 256, rb8 = (r + 8) * 256;
                const uint32_t g0 = (((uint32_t)(kb * 2)     ^ x7) * 8 + acol_in) * 4;
                const uint32_t g1 = (((uint32_t)(kb * 2 + 1) ^ x7) * 8 + acol_in) * 4;
                float2 p0 = *(const float2*)(XS + rb0 + g0);
                float2 p1 = *(const float2*)(XS + rb8 + g0);
                float2 p2 = *(const float2*)(XS + rb0 + g1);
                float2 p3 = *(const float2*)(XS + rb8 + g1);
                split2(p0.x, p0.y, ah[t][0], al[t][0]);
                split2(p1.x, p1.y, ah[t][1], al[t][1]);
                split2(p2.x, p2.y, ah[t][2], al[t][2]);
                split2(p3.x, p3.y, ah[t][3], al[t][3]);
            }
            #pragma unroll
            for (int nb2 = 0; nb2 < 3; ++nb2) {
                uint32_t bh[4], bl[4];
                uint32_t row = (uint32_t)(wn * 48 + nb2 * 16) + brow_in;
                uint32_t off = sw(row * 128 + kb * 32 + bcolsel);
                ldsm4(bh, bb + PJ_WH + off);
                ldsm4(bl, bb + PJ_WL + off);
                #pragma unroll
                for (int t = 0; t < 2; ++t) {
                    mma16816(acc[t][2 * nb2],     ah[t], bh);
                    mma16816(acc[t][2 * nb2],     ah[t], bl);
                    mma16816(acc[t][2 * nb2],     al[t], bh);
                    mma16816(acc[t][2 * nb2 + 1], ah[t], bh + 2);
                    mma16816(acc[t][2 * nb2 + 1], ah[t], bl + 2);
                    mma16816(acc[t][2 * nb2 + 1], al[t], bh + 2);
                }
            }
        }
        __syncthreads();
    }

    uint32_t* kh32 = (uint32_t*)g_kh; uint32_t* kl32 = (uint32_t*)g_kl;
    uint32_t* qh32 = (uint32_t*)g_qh; uint32_t* ql32 = (uint32_t*)g_ql;
    uint32_t* vh32 = (uint32_t*)g_vh; uint32_t* vl32 = (uint32_t*)g_vl;
    #pragma unroll
    for (int t = 0; t < 2; ++t) {
        const int r0 = m0 + wm * 32 + t * 16 + g;
        #pragma unroll
        for (int j = 0; j < 6; ++j) {
            const int ncol = n0 + wn * 48 + j * 8 + 2 * c;
            uint32_t h0, l0, h1, l1;
            split2(acc[t][j][0], acc[t][j][1], h0, l0);
            split2(acc[t][j][2], acc[t][j][3], h1, l1);
            uint32_t *dh, *dl;
            int c2;
            if (ncol < 64)       { dh = kh32; dl = kl32; c2 = ncol >> 1; }
            else if (ncol < 128) { dh = qh32; dl = ql32; c2 = (ncol - 64) >> 1; }
            else                 { dh = vh32; dl = vl32; c2 = (ncol - 128) >> 1; }
            dh[(size_t)r0 * 32 + c2] = h0;       dl[(size_t)r0 * 32 + c2] = l0;
            dh[(size_t)(r0 + 8) * 32 + c2] = h1; dl[(size_t)(r0 + 8) * 32 + c2] = l1;
        }
    }
}

// ======================= kernel 3: attention (R11 + per-kb fused softmax/PV) =
#define AT_BUF 32768
#define AT_KH  0
#define AT_KL  8192
#define AT_VH  16384
#define AT_VL  24576
#define AT_SMEM (2 * AT_BUF)

__global__ __launch_bounds__(128, 2)
void attn_kernel(float* __restrict__ out) {
    extern __shared__ char smem[];
    const uint32_t sbase = smem_u32(smem);
    const int tid = threadIdx.x;
    const int wid = tid >> 5, lane = tid & 31;
    const int g = lane >> 2, c = lane & 3;
    const int b = blockIdx.y;
    const int q0 = blockIdx.x * 64;

    // ---- Q fragments in registers (hi/lo), rows = q0 + wid*16 + {g, g+8} ----
    uint32_t qh[4][4], ql[4][4];
    {
        const uint32_t* qh32 = (const uint32_t*)g_qh;
        const uint32_t* ql32 = (const uint32_t*)g_ql;
        const size_t r0 = (size_t)(b * 2048 + q0 + wid * 16 + g) * 32;
        const size_t r1 = r0 + 8 * 32;
        #pragma unroll
        for (int kb = 0; kb < 4; ++kb) {
            const int c0 = kb * 8 + c;
            qh[kb][0] = qh32[r0 + c0];     qh[kb][1] = qh32[r1 + c0];
            qh[kb][2] = qh32[r0 + c0 + 4]; qh[kb][3] = qh32[r1 + c0 + 4];
            ql[kb][0] = ql32[r0 + c0];     ql[kb][1] = ql32[r1 + c0];
            ql[kb][2] = ql32[r0 + c0 + 4]; ql[kb][3] = ql32[r1 + c0 + 4];
        }
    }

    auto load_kv = [&](int kt, int buf) {
        const uint32_t bb = sbase + buf * AT_BUF;
        #pragma unroll
        for (int j = 0; j < 4; ++j) {
            int ch = tid + 128 * j;
            int row = ch >> 3, col16 = ch & 7;
            uint32_t d = sw((uint32_t)row * 128 + col16 * 16);
            size_t srcoff = (size_t)(b * 2048 + kt * 64 + row) * 64 + col16 * 8;
            cpa(bb + AT_KH + d, g_kh + srcoff);
            cpa(bb + AT_KL + d, g_kl + srcoff);
            cpa(bb + AT_VH + d, g_vh + srcoff);
            cpa(bb + AT_VL + d, g_vl + srcoff);
        }
    };

    float o[8][4];
    #pragma unroll
    for (int f = 0; f < 8; ++f)
        #pragma unroll
        for (int q = 0; q < 4; ++q) o[f][q] = 0.0f;
    float l0 = 0.0f, l1 = 0.0f;

    load_kv(0, 0);
    CP_COMMIT();

    const uint32_t kb_row_in = (uint32_t)(((lane >> 4) & 1) * 8 + (lane & 7));
    const uint32_t kb_colsel = ((lane >> 3) & 1) * 16;
    const uint32_t vb_row_in = (uint32_t)(((lane >> 3) & 1) * 8 + (lane & 7));

    for (int kt = 0; kt < 32; ++kt) {
        const int buf = kt & 1;
        if (kt < 31) { load_kv(kt + 1, buf ^ 1); CP_COMMIT(); CP_WAIT(1); }
        else         { CP_WAIT(0); }
        __syncthreads();
        const uint32_t bb = sbase + buf * AT_BUF;

        // ---- S = Q K^T (3-term) ----
        float s[8][4];
        #pragma unroll
        for (int f = 0; f < 8; ++f)
            #pragma unroll
            for (int q = 0; q < 4; ++q) s[f][q] = 0.0f;

        #pragma unroll
        for (int kb = 0; kb < 4; ++kb) {
            #pragma unroll
            for (int nb2 = 0; nb2 < 4; ++nb2) {
                uint32_t bh[4], bl[4];
                uint32_t row = (uint32_t)(nb2 * 16) + kb_row_in;
                uint32_t off = sw(row * 128 + kb * 32 + kb_colsel);
                ldsm4(bh, bb + AT_KH + off);
                ldsm4(bl, bb + AT_KL + off);
                mma16816(s[2 * nb2],     qh[kb], bh);
                mma16816(s[2 * nb2],     qh[kb], bl);
                mma16816(s[2 * nb2],     ql[kb], bh);
                mma16816(s[2 * nb2 + 1], qh[kb], bh + 2);
                mma16816(s[2 * nb2 + 1], qh[kb], bl + 2);
                mma16816(s[2 * nb2 + 1], ql[kb], bh + 2);
            }
        }

        // ---- per-kb fused: exp(kb) -> PV(kb); MUFU of kb+1 hides under
        //      the accumulator-serialized PV(kb) MMA chain ----
        #pragma unroll
        for (int kb = 0; kb < 4; ++kb) {
            uint32_t ph[4], pl[4];
            #pragma unroll
            for (int fo = 0; fo < 2; ++fo) {
                const int f = 2 * kb + fo;
                float p0 = __expf(s[f][0]), p1 = __expf(s[f][1]);
                float p2 = __expf(s[f][2]), p3 = __expf(s[f][3]);
                l0 += p0 + p1;
                l1 += p2 + p3;
                split2(p0, p1, ph[2 * fo], pl[2 * fo]);
                split2(p2, p3, ph[2 * fo + 1], pl[2 * fo + 1]);
            }
            #pragma unroll
            for (int nb2 = 0; nb2 < 4; ++nb2) {
                uint32_t vhf[4], vlf[4];
                uint32_t row = (uint32_t)(kb * 16) + vb_row_in;
                uint32_t off = sw(row * 128 + (2 * nb2 + (lane >> 4)) * 16);
                ldsm4t(vhf, bb + AT_VH + off);
                ldsm4t(vlf, bb + AT_VL + off);
                mma16816(o[2 * nb2],     ph, vhf);
                mma16816(o[2 * nb2],     ph, vlf);
                mma16816(o[2 * nb2],     pl, vhf);
                mma16816(o[2 * nb2 + 1], ph, vhf + 2);
                mma16816(o[2 * nb2 + 1], ph, vlf + 2);
                mma16816(o[2 * nb2 + 1], pl, vhf + 2);
            }
        }
        __syncthreads();
    }

    // ---- epilogue ----
    l0 += __shfl_xor_sync(0xffffffffu, l0, 1);
    l0 += __shfl_xor_sync(0xffffffffu, l0, 2);
    l1 += __shfl_xor_sync(0xffffffffu, l1, 1);
    l1 += __shfl_xor_sync(0xffffffffu, l1, 2);
    const float inv0 = 1.0f / l0, inv1 = 1.0f / l1;

    const int r0 = b * 2048 + q0 + wid * 16 + g;
    #pragma unroll
    for (int f = 0; f < 8; ++f) {
        const int col = f * 8 + 2 * c;
        float2 v0 = make_float2(o[f][0] * inv0, o[f][1] * inv0);
        float2 v1 = make_float2(o[f][2] * inv1, o[f][3] * inv1);
        *(float2*)(out + (size_t)r0 * 64 + col)       = v0;
        *(float2*)(out + (size_t)(r0 + 8) * 64 + col) = v1;
    }
}

// ======================= launch =======================
extern "C" void kernel_launch(void* const* d_in, const int* in_sizes, int n_in,
                              void* d_out, int out_size) {
    const float* x  = (const float*)d_in[0];
    const float* Wk = (const float*)d_in[1];
    const float* Wq = (const float*)d_in[2];
    const float* Wv = (const float*)d_in[3];
    float* out = (float*)d_out;

    cudaFuncSetAttribute(proj_kernel, cudaFuncAttributeMaxDynamicSharedMemorySize, PJ_SMEM);
    cudaFuncSetAttribute(attn_kernel, cudaFuncAttributeMaxDynamicSharedMemorySize, AT_SMEM);

    wsplit_kernel<<<192, 256>>>(Wk, Wq, Wv);
    proj_kernel<<<dim3(128, 2), 256, PJ_SMEM>>>(x);
    attn_kernel<<<dim3(32, 8), 128, AT_SMEM>>>(out);
}

// round 14
// speedup vs baseline: 1.1715x; 1.1030x over previous
#include <cuda_runtime.h>
#include <cuda_bf16.h>
#include <cuda_fp16.h>
#include <cstdint>

#define DI __device__ __forceinline__

// ======================= scratch =======================
__device__ __nv_bfloat16 g_wh[192 * 1024], g_wl[192 * 1024];
__device__ __nv_bfloat16 g_kh[16384 * 64], g_kl[16384 * 64];
__device__ __nv_bfloat16 g_qh[16384 * 64], g_ql[16384 * 64];
__device__ __half g_vh[16384 * 64], g_vl[16384 * 64];   // V: fp16 hi/lo (PV 2-term)

// ======================= helpers =======================
DI uint32_t smem_u32(const void* p) {
    uint32_t a;
    asm("{ .reg .u64 t; cvta.to.shared.u64 t, %1; cvt.u32.u64 %0, t; }" : "=r"(a) : "l"(p));
    return a;
}
DI uint32_t sw(uint32_t o) { return o ^ ((o >> 3) & 0x70); }  // SW128 swizzle (bf16 tiles)

// fast bf16 split: hi = truncate-to-bf16 (exact residual), lo = rn(residual pair).
DI void split2(float a, float b, uint32_t& h, uint32_t& l) {
    uint32_t ua = __float_as_uint(a), ub = __float_as_uint(b);
    asm("prmt.b32 %0, %1, %2, 0x7632;" : "=r"(h) : "r"(ua), "r"(ub));
    float ra = a - __uint_as_float(ua & 0xFFFF0000u);
    float rb = b - __uint_as_float(ub & 0xFFFF0000u);
    asm("cvt.rn.bf16x2.f32 %0, %1, %2;" : "=r"(l) : "f"(rb), "f"(ra));
}
// fp16 hi/lo split (V path): hi = rn(a), lo = rn(a - hi); error ~2^-24
DI void splith2(float a, float b, uint32_t& h, uint32_t& l) {
    __half ha = __float2half_rn(a), hb = __float2half_rn(b);
    float ra = a - __half2float(ha);
    float rb = b - __half2float(hb);
    h = ((uint32_t)__half_as_ushort(hb) << 16) | (uint32_t)__half_as_ushort(ha);
    asm("cvt.rn.f16x2.f32 %0, %1, %2;" : "=r"(l) : "f"(rb), "f"(ra));
}
DI uint32_t packh(float a, float b) {   // a -> low half, b -> high half (fp16x2)
    uint32_t r;
    asm("cvt.rn.f16x2.f32 %0, %1, %2;" : "=r"(r) : "f"(b), "f"(a));
    return r;
}

DI void mma16816(float* d, const uint32_t* a, const uint32_t* b) {
    asm volatile(
        "mma.sync.aligned.m16n8k16.row.col.f32.bf16.bf16.f32 "
        "{%0,%1,%2,%3}, {%4,%5,%6,%7}, {%8,%9}, {%0,%1,%2,%3};"
        : "+f"(d[0]), "+f"(d[1]), "+f"(d[2]), "+f"(d[3])
        : "r"(a[0]), "r"(a[1]), "r"(a[2]), "r"(a[3]), "r"(b[0]), "r"(b[1]));
}
DI void mma16816h(float* d, const uint32_t* a, const uint32_t* b) {
    asm volatile(
        "mma.sync.aligned.m16n8k16.row.col.f32.f16.f16.f32 "
        "{%0,%1,%2,%3}, {%4,%5,%6,%7}, {%8,%9}, {%0,%1,%2,%3};"
        : "+f"(d[0]), "+f"(d[1]), "+f"(d[2]), "+f"(d[3])
        : "r"(a[0]), "r"(a[1]), "r"(a[2]), "r"(a[3]), "r"(b[0]), "r"(b[1]));
}
DI void ldsm4(uint32_t* r, uint32_t addr) {
    asm volatile("ldmatrix.sync.aligned.m8n8.x4.shared.b16 {%0,%1,%2,%3}, [%4];"
                 : "=r"(r[0]), "=r"(r[1]), "=r"(r[2]), "=r"(r[3]) : "r"(addr));
}
DI void ldsm4t(uint32_t* r, uint32_t addr) {
    asm volatile("ldmatrix.sync.aligned.m8n8.x4.trans.shared.b16 {%0,%1,%2,%3}, [%4];"
                 : "=r"(r[0]), "=r"(r[1]), "=r"(r[2]), "=r"(r[3]) : "r"(addr));
}
DI void cpa(uint32_t dst, const void* src) {
    asm volatile("cp.async.cg.shared.global [%0], [%1], 16;" :: "r"(dst), "l"(src));
}
#define CP_COMMIT()  asm volatile("cp.async.commit_group;" ::: "memory")
#define CP_WAIT(n)   asm volatile("cp.async.wait_group %0;" :: "n"(n) : "memory")

// ======================= kernel 1: W split (tiny) =======================
__global__ void wsplit_kernel(const float* __restrict__ Wk,
                              const float* __restrict__ Wq,
                              const float* __restrict__ Wv) {
    const int idx = blockIdx.x * 256 + threadIdx.x;   // 49152 float4s
    int r = idx >> 8;
    const float* src = (r < 64) ? Wk : (r < 128) ? Wq : Wv;
    float sc = (r >= 64 && r < 128) ? 0.125f : 1.0f;  // fold 1/sqrt(64) into Q
    float4 f = ((const float4*)(src + (size_t)(r & 63) * 1024))[idx & 255];
    uint2 h, l;
    split2(f.x * sc, f.y * sc, h.x, l.x);
    split2(f.z * sc, f.w * sc, h.y, l.y);
    ((uint2*)g_wh)[idx] = h;
    ((uint2*)g_wl)[idx] = l;
}

// ======================= kernel 2: projection (x split fused, R11) ==========
#define PJ_BUF 57344
#define PJ_XS  0
#define PJ_WH  32768
#define PJ_WL  45056
#define PJ_SMEM (2 * PJ_BUF)

__global__ __launch_bounds__(256, 2)
void proj_kernel(const float* __restrict__ x) {
    extern __shared__ char smem[];
    const uint32_t sbase = smem_u32(smem);
    const int tid = threadIdx.x;
    const int wid = tid >> 5, lane = tid & 31;
    const int wm = wid >> 1, wn = wid & 1;
    const int g = lane >> 2, c = lane & 3;
    const int m0 = blockIdx.x * 128;
    const int n0 = blockIdx.y * 96;

    auto load_step = [&](int s, int buf) {
        const int k0 = s * 64;
        const uint32_t bb = sbase + buf * PJ_BUF;
        #pragma unroll
        for (int j = 0; j < 8; ++j) {
            int ch = tid + 256 * j;
            int row = ch >> 4, c16 = ch & 15;
            uint32_t d = (uint32_t)row * 256 +
                         ((((uint32_t)(c16 >> 1) ^ ((uint32_t)row & 7)) * 8 + (c16 & 1) * 4) * 4);
            cpa(bb + PJ_XS + d, x + (size_t)(m0 + row) * 1024 + k0 + c16 * 4);
        }
        #pragma unroll
        for (int j = 0; j < 3; ++j) {
            int ch = tid + 256 * j;
            int row = ch >> 3, col16 = ch & 7;
            uint32_t d = sw((uint32_t)row * 128 + col16 * 16);
            size_t srcoff = (size_t)(n0 + row) * 1024 + k0 + col16 * 8;
            cpa(bb + PJ_WH + d, g_wh + srcoff);
            cpa(bb + PJ_WL + d, g_wl + srcoff);
        }
    };

    float acc[2][6][4];
    #pragma unroll
    for (int t = 0; t < 2; ++t)
        #pragma unroll
        for (int j = 0; j < 6; ++j)
            #pragma unroll
            for (int q = 0; q < 4; ++q) acc[t][j][q] = 0.0f;

    load_step(0, 0);
    CP_COMMIT();

    const uint32_t brow_in = (uint32_t)(((lane >> 4) & 1) * 8 + (lane & 7));
    const uint32_t bcolsel = ((lane >> 3) & 1) * 16;
    const uint32_t arow_lo = (uint32_t)(wm * 32 + (lane >> 2));
    const uint32_t acol_in = (uint32_t)((lane & 3) * 2);

    for (int s = 0; s < 16; ++s) {
        const int buf = s & 1;
        if (s < 15) { load_step(s + 1, buf ^ 1); CP_COMMIT(); CP_WAIT(1); }
        else        { CP_WAIT(0); }
        __syncthreads();

        const uint32_t bb = sbase + buf * PJ_BUF;
        const char* XS = smem + buf * PJ_BUF + PJ_XS;

        #pragma unroll
        for (int kb = 0; kb < 4; ++kb) {
            uint32_t ah[2][4], al[2][4];
            #pragma unroll
            for (int t = 0; t < 2; ++t) {
                const uint32_t r = arow_lo + t * 16;
                const uint32_t x7 = r & 7;
                const uint32_t rb0 = r * 256, rb8 = (r + 8) * 256;
                const uint32_t g0 = (((uint32_t)(kb * 2)     ^ x7) * 8 + acol_in) * 4;
                const uint32_t g1 = (((uint32_t)(kb * 2 + 1) ^ x7) * 8 + acol_in) * 4;
                float2 p0 = *(const float2*)(XS + rb0 + g0);
                float2 p1 = *(const float2*)(XS + rb8 + g0);
                float2 p2 = *(const float2*)(XS + rb0 + g1);
                float2 p3 = *(const float2*)(XS + rb8 + g1);
                split2(p0.x, p0.y, ah[t][0], al[t][0]);
                split2(p1.x, p1.y, ah[t][1], al[t][1]);
                split2(p2.x, p2.y, ah[t][2], al[t][2]);
                split2(p3.x, p3.y, ah[t][3], al[t][3]);
            }
            #pragma unroll
            for (int nb2 = 0; nb2 < 3; ++nb2) {
                uint32_t bh[4], bl[4];
                uint32_t row = (uint32_t)(wn * 48 + nb2 * 16) + brow_in;
                uint32_t off = sw(row * 128 + kb * 32 + bcolsel);
                ldsm4(bh, bb + PJ_WH + off);
                ldsm4(bl, bb + PJ_WL + off);
                #pragma unroll
                for (int t = 0; t < 2; ++t) {
                    mma16816(acc[t][2 * nb2],     ah[t], bh);
                    mma16816(acc[t][2 * nb2],     ah[t], bl);
                    mma16816(acc[t][2 * nb2],     al[t], bh);
                    mma16816(acc[t][2 * nb2 + 1], ah[t], bh + 2);
                    mma16816(acc[t][2 * nb2 + 1], ah[t], bl + 2);
                    mma16816(acc[t][2 * nb2 + 1], al[t], bh + 2);
                }
            }
        }
        __syncthreads();
    }

    uint32_t* kh32 = (uint32_t*)g_kh; uint32_t* kl32 = (uint32_t*)g_kl;
    uint32_t* qh32 = (uint32_t*)g_qh; uint32_t* ql32 = (uint32_t*)g_ql;
    uint32_t* vh32 = (uint32_t*)g_vh; uint32_t* vl32 = (uint32_t*)g_vl;
    #pragma unroll
    for (int t = 0; t < 2; ++t) {
        const int r0 = m0 + wm * 32 + t * 16 + g;
        #pragma unroll
        for (int j = 0; j < 6; ++j) {
            const int ncol = n0 + wn * 48 + j * 8 + 2 * c;
            uint32_t h0, l0, h1, l1;
            uint32_t *dh, *dl;
            int c2;
            if (ncol < 128) {
                split2(acc[t][j][0], acc[t][j][1], h0, l0);
                split2(acc[t][j][2], acc[t][j][3], h1, l1);
                if (ncol < 64) { dh = kh32; dl = kl32; c2 = ncol >> 1; }
                else           { dh = qh32; dl = ql32; c2 = (ncol - 64) >> 1; }
            } else {
                splith2(acc[t][j][0], acc[t][j][1], h0, l0);
                splith2(acc[t][j][2], acc[t][j][3], h1, l1);
                dh = vh32; dl = vl32; c2 = (ncol - 128) >> 1;
            }
            dh[(size_t)r0 * 32 + c2] = h0;       dl[(size_t)r0 * 32 + c2] = l0;
            dh[(size_t)(r0 + 8) * 32 + c2] = h1; dl[(size_t)(r0 + 8) * 32 + c2] = l1;
        }
    }
}

// ======================= kernel 3: attention (PV = fp16 2-term) =============
#define AT_BUF 32768
#define AT_KH  0
#define AT_KL  8192
#define AT_VH  16384
#define AT_VL  24576
#define AT_SMEM (2 * AT_BUF)

__global__ __launch_bounds__(128, 2)
void attn_kernel(float* __restrict__ out) {
    extern __shared__ char smem[];
    const uint32_t sbase = smem_u32(smem);
    const int tid = threadIdx.x;
    const int wid = tid >> 5, lane = tid & 31;
    const int g = lane >> 2, c = lane & 3;
    const int b = blockIdx.y;
    const int q0 = blockIdx.x * 64;

    // ---- Q fragments in registers (hi/lo), rows = q0 + wid*16 + {g, g+8} ----
    uint32_t qh[4][4], ql[4][4];
    {
        const uint32_t* qh32 = (const uint32_t*)g_qh;
        const uint32_t* ql32 = (const uint32_t*)g_ql;
        const size_t r0 = (size_t)(b * 2048 + q0 + wid * 16 + g) * 32;
        const size_t r1 = r0 + 8 * 32;
        #pragma unroll
        for (int kb = 0; kb < 4; ++kb) {
            const int c0 = kb * 8 + c;
            qh[kb][0] = qh32[r0 + c0];     qh[kb][1] = qh32[r1 + c0];
            qh[kb][2] = qh32[r0 + c0 + 4]; qh[kb][3] = qh32[r1 + c0 + 4];
            ql[kb][0] = ql32[r0 + c0];     ql[kb][1] = ql32[r1 + c0];
            ql[kb][2] = ql32[r0 + c0 + 4]; ql[kb][3] = ql32[r1 + c0 + 4];
        }
    }

    auto load_kv = [&](int kt, int buf) {
        const uint32_t bb = sbase + buf * AT_BUF;
        #pragma unroll
        for (int j = 0; j < 4; ++j) {
            int ch = tid + 128 * j;
            int row = ch >> 3, col16 = ch & 7;
            uint32_t d = sw((uint32_t)row * 128 + col16 * 16);
            size_t srcoff = (size_t)(b * 2048 + kt * 64 + row) * 64 + col16 * 8;
            cpa(bb + AT_KH + d, g_kh + srcoff);
            cpa(bb + AT_KL + d, g_kl + srcoff);
            cpa(bb + AT_VH + d, g_vh + srcoff);
            cpa(bb + AT_VL + d, g_vl + srcoff);
        }
    };

    float o[8][4];
    #pragma unroll
    for (int f = 0; f < 8; ++f)
        #pragma unroll
        for (int q = 0; q < 4; ++q) o[f][q] = 0.0f;
    float l0 = 0.0f, l1 = 0.0f;

    load_kv(0, 0);
    CP_COMMIT();

    const uint32_t kb_row_in = (uint32_t)(((lane >> 4) & 1) * 8 + (lane & 7));
    const uint32_t kb_colsel = ((lane >> 3) & 1) * 16;
    const uint32_t vb_row_in = (uint32_t)(((lane >> 3) & 1) * 8 + (lane & 7));

    for (int kt = 0; kt < 32; ++kt) {
        const int buf = kt & 1;
        if (kt < 31) { load_kv(kt + 1, buf ^ 1); CP_COMMIT(); CP_WAIT(1); }
        else         { CP_WAIT(0); }
        __syncthreads();
        const uint32_t bb = sbase + buf * AT_BUF;

        // ---- S = Q K^T (bf16 3-term) ----
        float s[8][4];
        #pragma unroll
        for (int f = 0; f < 8; ++f)
            #pragma unroll
            for (int q = 0; q < 4; ++q) s[f][q] = 0.0f;

        #pragma unroll
        for (int kb = 0; kb < 4; ++kb) {
            #pragma unroll
            for (int nb2 = 0; nb2 < 4; ++nb2) {
                uint32_t bh[4], bl[4];
                uint32_t row = (uint32_t)(nb2 * 16) + kb_row_in;
                uint32_t off = sw(row * 128 + kb * 32 + kb_colsel);
                ldsm4(bh, bb + AT_KH + off);
                ldsm4(bl, bb + AT_KL + off);
                mma16816(s[2 * nb2],     qh[kb], bh);
                mma16816(s[2 * nb2],     qh[kb], bl);
                mma16816(s[2 * nb2],     ql[kb], bh);
                mma16816(s[2 * nb2 + 1], qh[kb], bh + 2);
                mma16816(s[2 * nb2 + 1], qh[kb], bl + 2);
                mma16816(s[2 * nb2 + 1], ql[kb], bh + 2);
            }
        }

        // ---- per-kb fused: exp(kb) -> PV(kb); P single fp16, V fp16 2-term ----
        #pragma unroll
        for (int kb = 0; kb < 4; ++kb) {
            uint32_t ph[4];
            #pragma unroll
            for (int fo = 0; fo < 2; ++fo) {
                const int f = 2 * kb + fo;
                float p0 = __expf(s[f][0]), p1 = __expf(s[f][1]);
                float p2 = __expf(s[f][2]), p3 = __expf(s[f][3]);
                l0 += p0 + p1;
                l1 += p2 + p3;
                ph[2 * fo]     = packh(p0, p1);
                ph[2 * fo + 1] = packh(p2, p3);
            }
            #pragma unroll
            for (int nb2 = 0; nb2 < 4; ++nb2) {
                uint32_t vhf[4], vlf[4];
                uint32_t row = (uint32_t)(kb * 16) + vb_row_in;
                uint32_t off = sw(row * 128 + (2 * nb2 + (lane >> 4)) * 16);
                ldsm4t(vhf, bb + AT_VH + off);
                ldsm4t(vlf, bb + AT_VL + off);
                mma16816h(o[2 * nb2],     ph, vhf);
                mma16816h(o[2 * nb2],     ph, vlf);
                mma16816h(o[2 * nb2 + 1], ph, vhf + 2);
                mma16816h(o[2 * nb2 + 1], ph, vlf + 2);
            }
        }
        __syncthreads();
    }

    // ---- epilogue ----
    l0 += __shfl_xor_sync(0xffffffffu, l0, 1);
    l0 += __shfl_xor_sync(0xffffffffu, l0, 2);
    l1 += __shfl_xor_sync(0xffffffffu, l1, 1);
    l1 += __shfl_xor_sync(0xffffffffu, l1, 2);
    const float inv0 = 1.0f / l0, inv1 = 1.0f / l1;

    const int r0 = b * 2048 + q0 + wid * 16 + g;
    #pragma unroll
    for (int f = 0; f < 8; ++f) {
        const int col = f * 8 + 2 * c;
        float2 v0 = make_float2(o[f][0] * inv0, o[f][1] * inv0);
        float2 v1 = make_float2(o[f][2] * inv1, o[f][3] * inv1);
        *(float2*)(out + (size_t)r0 * 64 + col)       = v0;
        *(float2*)(out + (size_t)(r0 + 8) * 64 + col) = v1;
    }
}

// ======================= launch =======================
extern "C" void kernel_launch(void* const* d_in, const int* in_sizes, int n_in,
                              void* d_out, int out_size) {
    const float* x  = (const float*)d_in[0];
    const float* Wk = (const float*)d_in[1];
    const float* Wq = (const float*)d_in[2];
    const float* Wv = (const float*)d_in[3];
    float* out = (float*)d_out;

    cudaFuncSetAttribute(proj_kernel, cudaFuncAttributeMaxDynamicSharedMemorySize, PJ_SMEM);
    cudaFuncSetAttribute(attn_kernel, cudaFuncAttributeMaxDynamicSharedMemorySize, AT_SMEM);

    wsplit_kernel<<<192, 256>>>(Wk, Wq, Wv);
    proj_kernel<<<dim3(128, 2), 256, PJ_SMEM>>>(x);
    attn_kernel<<<dim3(32, 8), 128, AT_SMEM>>>(out);
}

// round 15
// speedup vs baseline: 1.2811x; 1.0936x over previous
#include <cuda_runtime.h>
#include <cuda_bf16.h>
#include <cuda_fp16.h>
#include <cstdint>

#define DI __device__ __forceinline__

// ======================= scratch =======================
__device__ __nv_bfloat16 g_wh[192 * 1024], g_wl[192 * 1024];
__device__ __nv_bfloat16 g_kh[16384 * 64], g_kl[16384 * 64];
__device__ __nv_bfloat16 g_qh[16384 * 64], g_ql[16384 * 64];
__device__ __half g_vh[16384 * 64];   // V: single fp16 (PV 1-term on V side)

// ======================= helpers =======================
DI uint32_t smem_u32(const void* p) {
    uint32_t a;
    asm("{ .reg .u64 t; cvta.to.shared.u64 t, %1; cvt.u32.u64 %0, t; }" : "=r"(a) : "l"(p));
    return a;
}
DI uint32_t sw(uint32_t o) { return o ^ ((o >> 3) & 0x70); }  // SW128 swizzle (bf16 tiles)

// fast bf16 split: hi = truncate-to-bf16 (exact residual), lo = rn(residual pair).
DI void split2(float a, float b, uint32_t& h, uint32_t& l) {
    uint32_t ua = __float_as_uint(a), ub = __float_as_uint(b);
    asm("prmt.b32 %0, %1, %2, 0x7632;" : "=r"(h) : "r"(ua), "r"(ub));
    float ra = a - __uint_as_float(ua & 0xFFFF0000u);
    float rb = b - __uint_as_float(ub & 0xFFFF0000u);
    asm("cvt.rn.bf16x2.f32 %0, %1, %2;" : "=r"(l) : "f"(rb), "f"(ra));
}
DI uint32_t packh(float a, float b) {   // a -> low half, b -> high half (fp16x2)
    uint32_t r;
    asm("cvt.rn.f16x2.f32 %0, %1, %2;" : "=r"(r) : "f"(b), "f"(a));
    return r;
}

DI void mma16816(float* d, const uint32_t* a, const uint32_t* b) {
    asm volatile(
        "mma.sync.aligned.m16n8k16.row.col.f32.bf16.bf16.f32 "
        "{%0,%1,%2,%3}, {%4,%5,%6,%7}, {%8,%9}, {%0,%1,%2,%3};"
        : "+f"(d[0]), "+f"(d[1]), "+f"(d[2]), "+f"(d[3])
        : "r"(a[0]), "r"(a[1]), "r"(a[2]), "r"(a[3]), "r"(b[0]), "r"(b[1]));
}
DI void mma16816h(float* d, const uint32_t* a, const uint32_t* b) {
    asm volatile(
        "mma.sync.aligned.m16n8k16.row.col.f32.f16.f16.f32 "
        "{%0,%1,%2,%3}, {%4,%5,%6,%7}, {%8,%9}, {%0,%1,%2,%3};"
        : "+f"(d[0]), "+f"(d[1]), "+f"(d[2]), "+f"(d[3])
        : "r"(a[0]), "r"(a[1]), "r"(a[2]), "r"(a[3]), "r"(b[0]), "r"(b[1]));
}
DI void ldsm4(uint32_t* r, uint32_t addr) {
    asm volatile("ldmatrix.sync.aligned.m8n8.x4.shared.b16 {%0,%1,%2,%3}, [%4];"
                 : "=r"(r[0]), "=r"(r[1]), "=r"(r[2]), "=r"(r[3]) : "r"(addr));
}
DI void ldsm4t(uint32_t* r, uint32_t addr) {
    asm volatile("ldmatrix.sync.aligned.m8n8.x4.trans.shared.b16 {%0,%1,%2,%3}, [%4];"
                 : "=r"(r[0]), "=r"(r[1]), "=r"(r[2]), "=r"(r[3]) : "r"(addr));
}
DI void cpa(uint32_t dst, const void* src) {
    asm volatile("cp.async.cg.shared.global [%0], [%1], 16;" :: "r"(dst), "l"(src));
}
#define CP_COMMIT()  asm volatile("cp.async.commit_group;" ::: "memory")
#define CP_WAIT(n)   asm volatile("cp.async.wait_group %0;" :: "n"(n) : "memory")

// ======================= kernel 1: W split (tiny) =======================
__global__ void wsplit_kernel(const float* __restrict__ Wk,
                              const float* __restrict__ Wq,
                              const float* __restrict__ Wv) {
    const int idx = blockIdx.x * 256 + threadIdx.x;   // 49152 float4s
    int r = idx >> 8;
    const float* src = (r < 64) ? Wk : (r < 128) ? Wq : Wv;
    float sc = (r >= 64 && r < 128) ? 0.125f : 1.0f;  // fold 1/sqrt(64) into Q
    float4 f = ((const float4*)(src + (size_t)(r & 63) * 1024))[idx & 255];
    uint2 h, l;
    split2(f.x * sc, f.y * sc, h.x, l.x);
    split2(f.z * sc, f.w * sc, h.y, l.y);
    ((uint2*)g_wh)[idx] = h;
    ((uint2*)g_wl)[idx] = l;
}

// ======================= kernel 2: projection (x split fused, R11) ==========
#define PJ_BUF 57344
#define PJ_XS  0
#define PJ_WH  32768
#define PJ_WL  45056
#define PJ_SMEM (2 * PJ_BUF)

__global__ __launch_bounds__(256, 2)
void proj_kernel(const float* __restrict__ x) {
    extern __shared__ char smem[];
    const uint32_t sbase = smem_u32(smem);
    const int tid = threadIdx.x;
    const int wid = tid >> 5, lane = tid & 31;
    const int wm = wid >> 1, wn = wid & 1;
    const int g = lane >> 2, c = lane & 3;
    const int m0 = blockIdx.x * 128;
    const int n0 = blockIdx.y * 96;

    auto load_step = [&](int s, int buf) {
        const int k0 = s * 64;
        const uint32_t bb = sbase + buf * PJ_BUF;
        #pragma unroll
        for (int j = 0; j < 8; ++j) {
            int ch = tid + 256 * j;
            int row = ch >> 4, c16 = ch & 15;
            uint32_t d = (uint32_t)row * 256 +
                         ((((uint32_t)(c16 >> 1) ^ ((uint32_t)row & 7)) * 8 + (c16 & 1) * 4) * 4);
            cpa(bb + PJ_XS + d, x + (size_t)(m0 + row) * 1024 + k0 + c16 * 4);
        }
        #pragma unroll
        for (int j = 0; j < 3; ++j) {
            int ch = tid + 256 * j;
            int row = ch >> 3, col16 = ch & 7;
            uint32_t d = sw((uint32_t)row * 128 + col16 * 16);
            size_t srcoff = (size_t)(n0 + row) * 1024 + k0 + col16 * 8;
            cpa(bb + PJ_WH + d, g_wh + srcoff);
            cpa(bb + PJ_WL + d, g_wl + srcoff);
        }
    };

    float acc[2][6][4];
    #pragma unroll
    for (int t = 0; t < 2; ++t)
        #pragma unroll
        for (int j = 0; j < 6; ++j)
            #pragma unroll
            for (int q = 0; q < 4; ++q) acc[t][j][q] = 0.0f;

    load_step(0, 0);
    CP_COMMIT();

    const uint32_t brow_in = (uint32_t)(((lane >> 4) & 1) * 8 + (lane & 7));
    const uint32_t bcolsel = ((lane >> 3) & 1) * 16;
    const uint32_t arow_lo = (uint32_t)(wm * 32 + (lane >> 2));
    const uint32_t acol_in = (uint32_t)((lane & 3) * 2);

    for (int s = 0; s < 16; ++s) {
        const int buf = s & 1;
        if (s < 15) { load_step(s + 1, buf ^ 1); CP_COMMIT(); CP_WAIT(1); }
        else        { CP_WAIT(0); }
        __syncthreads();

        const uint32_t bb = sbase + buf * PJ_BUF;
        const char* XS = smem + buf * PJ_BUF + PJ_XS;

        #pragma unroll
        for (int kb = 0; kb < 4; ++kb) {
            uint32_t ah[2][4], al[2][4];
            #pragma unroll
            for (int t = 0; t < 2; ++t) {
                const uint32_t r = arow_lo + t * 16;
                const uint32_t x7 = r & 7;
                const uint32_t rb0 = r * 256, rb8 = (r + 8) * 256;
                const uint32_t g0 = (((uint32_t)(kb * 2)     ^ x7) * 8 + acol_in) * 4;
                const uint32_t g1 = (((uint32_t)(kb * 2 + 1) ^ x7) * 8 + acol_in) * 4;
                float2 p0 = *(const float2*)(XS + rb0 + g0);
                float2 p1 = *(const float2*)(XS + rb8 + g0);
                float2 p2 = *(const float2*)(XS + rb0 + g1);
                float2 p3 = *(const float2*)(XS + rb8 + g1);
                split2(p0.x, p0.y, ah[t][0], al[t][0]);
                split2(p1.x, p1.y, ah[t][1], al[t][1]);
                split2(p2.x, p2.y, ah[t][2], al[t][2]);
                split2(p3.x, p3.y, ah[t][3], al[t][3]);
            }
            #pragma unroll
            for (int nb2 = 0; nb2 < 3; ++nb2) {
                uint32_t bh[4], bl[4];
                uint32_t row = (uint32_t)(wn * 48 + nb2 * 16) + brow_in;
                uint32_t off = sw(row * 128 + kb * 32 + bcolsel);
                ldsm4(bh, bb + PJ_WH + off);
                ldsm4(bl, bb + PJ_WL + off);
                #pragma unroll
                for (int t = 0; t < 2; ++t) {
                    mma16816(acc[t][2 * nb2],     ah[t], bh);
                    mma16816(acc[t][2 * nb2],     ah[t], bl);
                    mma16816(acc[t][2 * nb2],     al[t], bh);
                    mma16816(acc[t][2 * nb2 + 1], ah[t], bh + 2);
                    mma16816(acc[t][2 * nb2 + 1], ah[t], bl + 2);
                    mma16816(acc[t][2 * nb2 + 1], al[t], bh + 2);
                }
            }
        }
        __syncthreads();
    }

    uint32_t* kh32 = (uint32_t*)g_kh; uint32_t* kl32 = (uint32_t*)g_kl;
    uint32_t* qh32 = (uint32_t*)g_qh; uint32_t* ql32 = (uint32_t*)g_ql;
    uint32_t* vh32 = (uint32_t*)g_vh;
    #pragma unroll
    for (int t = 0; t < 2; ++t) {
        const int r0 = m0 + wm * 32 + t * 16 + g;
        #pragma unroll
        for (int j = 0; j < 6; ++j) {
            const int ncol = n0 + wn * 48 + j * 8 + 2 * c;
            if (ncol < 128) {
                uint32_t h0, l0, h1, l1;
                split2(acc[t][j][0], acc[t][j][1], h0, l0);
                split2(acc[t][j][2], acc[t][j][3], h1, l1);
                uint32_t *dh, *dl;
                int c2;
                if (ncol < 64) { dh = kh32; dl = kl32; c2 = ncol >> 1; }
                else           { dh = qh32; dl = ql32; c2 = (ncol - 64) >> 1; }
                dh[(size_t)r0 * 32 + c2] = h0;       dl[(size_t)r0 * 32 + c2] = l0;
                dh[(size_t)(r0 + 8) * 32 + c2] = h1; dl[(size_t)(r0 + 8) * 32 + c2] = l1;
            } else {
                int c2 = (ncol - 128) >> 1;
                vh32[(size_t)r0 * 32 + c2]       = packh(acc[t][j][0], acc[t][j][1]);
                vh32[(size_t)(r0 + 8) * 32 + c2] = packh(acc[t][j][2], acc[t][j][3]);
            }
        }
    }
}

// ======================= kernel 3: attention (PV = fp16 x fp16, 1 term) =====
#define AT_BUF 24576
#define AT_KH  0
#define AT_KL  8192
#define AT_VH  16384
#define AT_SMEM (2 * AT_BUF)

__global__ __launch_bounds__(128, 2)
void attn_kernel(float* __restrict__ out) {
    extern __shared__ char smem[];
    const uint32_t sbase = smem_u32(smem);
    const int tid = threadIdx.x;
    const int wid = tid >> 5, lane = tid & 31;
    const int g = lane >> 2, c = lane & 3;
    const int b = blockIdx.y;
    const int q0 = blockIdx.x * 64;

    // ---- Q fragments in registers (hi/lo), rows = q0 + wid*16 + {g, g+8} ----
    uint32_t qh[4][4], ql[4][4];
    {
        const uint32_t* qh32 = (const uint32_t*)g_qh;
        const uint32_t* ql32 = (const uint32_t*)g_ql;
        const size_t r0 = (size_t)(b * 2048 + q0 + wid * 16 + g) * 32;
        const size_t r1 = r0 + 8 * 32;
        #pragma unroll
        for (int kb = 0; kb < 4; ++kb) {
            const int c0 = kb * 8 + c;
            qh[kb][0] = qh32[r0 + c0];     qh[kb][1] = qh32[r1 + c0];
            qh[kb][2] = qh32[r0 + c0 + 4]; qh[kb][3] = qh32[r1 + c0 + 4];
            ql[kb][0] = ql32[r0 + c0];     ql[kb][1] = ql32[r1 + c0];
            ql[kb][2] = ql32[r0 + c0 + 4]; ql[kb][3] = ql32[r1 + c0 + 4];
        }
    }

    auto load_kv = [&](int kt, int buf) {
        const uint32_t bb = sbase + buf * AT_BUF;
        #pragma unroll
        for (int j = 0; j < 4; ++j) {
            int ch = tid + 128 * j;
            int row = ch >> 3, col16 = ch & 7;
            uint32_t d = sw((uint32_t)row * 128 + col16 * 16);
            size_t srcoff = (size_t)(b * 2048 + kt * 64 + row) * 64 + col16 * 8;
            cpa(bb + AT_KH + d, g_kh + srcoff);
            cpa(bb + AT_KL + d, g_kl + srcoff);
            cpa(bb + AT_VH + d, g_vh + srcoff);
        }
    };

    float o[8][4];
    #pragma unroll
    for (int f = 0; f < 8; ++f)
        #pragma unroll
        for (int q = 0; q < 4; ++q) o[f][q] = 0.0f;
    float l0 = 0.0f, l1 = 0.0f;

    load_kv(0, 0);
    CP_COMMIT();

    const uint32_t kb_row_in = (uint32_t)(((lane >> 4) & 1) * 8 + (lane & 7));
    const uint32_t kb_colsel = ((lane >> 3) & 1) * 16;
    const uint32_t vb_row_in = (uint32_t)(((lane >> 3) & 1) * 8 + (lane & 7));

    for (int kt = 0; kt < 32; ++kt) {
        const int buf = kt & 1;
        if (kt < 31) { load_kv(kt + 1, buf ^ 1); CP_COMMIT(); CP_WAIT(1); }
        else         { CP_WAIT(0); }
        __syncthreads();
        const uint32_t bb = sbase + buf * AT_BUF;

        // ---- S = Q K^T (bf16 3-term) ----
        float s[8][4];
        #pragma unroll
        for (int f = 0; f < 8; ++f)
            #pragma unroll
            for (int q = 0; q < 4; ++q) s[f][q] = 0.0f;

        #pragma unroll
        for (int kb = 0; kb < 4; ++kb) {
            #pragma unroll
            for (int nb2 = 0; nb2 < 4; ++nb2) {
                uint32_t bh[4], bl[4];
                uint32_t row = (uint32_t)(nb2 * 16) + kb_row_in;
                uint32_t off = sw(row * 128 + kb * 32 + kb_colsel);
                ldsm4(bh, bb + AT_KH + off);
                ldsm4(bl, bb + AT_KL + off);
                mma16816(s[2 * nb2],     qh[kb], bh);
                mma16816(s[2 * nb2],     qh[kb], bl);
                mma16816(s[2 * nb2],     ql[kb], bh);
                mma16816(s[2 * nb2 + 1], qh[kb], bh + 2);
                mma16816(s[2 * nb2 + 1], qh[kb], bl + 2);
                mma16816(s[2 * nb2 + 1], ql[kb], bh + 2);
            }
        }

        // ---- per-kb fused: exp(kb) -> PV(kb); P and V single fp16 ----
        #pragma unroll
        for (int kb = 0; kb < 4; ++kb) {
            uint32_t ph[4];
            #pragma unroll
            for (int fo = 0; fo < 2; ++fo) {
                const int f = 2 * kb + fo;
                float p0 = __expf(s[f][0]), p1 = __expf(s[f][1]);
                float p2 = __expf(s[f][2]), p3 = __expf(s[f][3]);
                l0 += p0 + p1;
                l1 += p2 + p3;
                ph[2 * fo]     = packh(p0, p1);
                ph[2 * fo + 1] = packh(p2, p3);
            }
            #pragma unroll
            for (int nb2 = 0; nb2 < 4; ++nb2) {
                uint32_t vhf[4];
                uint32_t row = (uint32_t)(kb * 16) + vb_row_in;
                uint32_t off = sw(row * 128 + (2 * nb2 + (lane >> 4)) * 16);
                ldsm4t(vhf, bb + AT_VH + off);
                mma16816h(o[2 * nb2],     ph, vhf);
                mma16816h(o[2 * nb2 + 1], ph, vhf + 2);
            }
        }
        __syncthreads();
    }

    // ---- epilogue ----
    l0 += __shfl_xor_sync(0xffffffffu, l0, 1);
    l0 += __shfl_xor_sync(0xffffffffu, l0, 2);
    l1 += __shfl_xor_sync(0xffffffffu, l1, 1);
    l1 += __shfl_xor_sync(0xffffffffu, l1, 2);
    const float inv0 = 1.0f / l0, inv1 = 1.0f / l1;

    const int r0 = b * 2048 + q0 + wid * 16 + g;
    #pragma unroll
    for (int f = 0; f < 8; ++f) {
        const int col = f * 8 + 2 * c;
        float2 v0 = make_float2(o[f][0] * inv0, o[f][1] * inv0);
        float2 v1 = make_float2(o[f][2] * inv1, o[f][3] * inv1);
        *(float2*)(out + (size_t)r0 * 64 + col)       = v0;
        *(float2*)(out + (size_t)(r0 + 8) * 64 + col) = v1;
    }
}

// ======================= launch =======================
extern "C" void kernel_launch(void* const* d_in, const int* in_sizes, int n_in,
                              void* d_out, int out_size) {
    const float* x  = (const float*)d_in[0];
    const float* Wk = (const float*)d_in[1];
    const float* Wq = (const float*)d_in[2];
    const float* Wv = (const float*)d_in[3];
    float* out = (float*)d_out;

    cudaFuncSetAttribute(proj_kernel, cudaFuncAttributeMaxDynamicSharedMemorySize, PJ_SMEM);
    cudaFuncSetAttribute(attn_kernel, cudaFuncAttributeMaxDynamicSharedMemorySize, AT_SMEM);

    wsplit_kernel<<<192, 256>>>(Wk, Wq, Wv);
    proj_kernel<<<dim3(128, 2), 256, PJ_SMEM>>>(x);
    attn_kernel<<<dim3(32, 8), 128, AT_SMEM>>>(out);
}

// round 16
// speedup vs baseline: 1.9293x; 1.5060x over previous
#include <cuda_runtime.h>
#include <cuda_bf16.h>
#include <cuda_fp16.h>
#include <cstdint>

#define DI __device__ __forceinline__

// ======================= scratch (all fp16) =======================
__device__ __half g_wh[192 * 1024], g_wl[192 * 1024];   // W: fp16 hi/lo (2-term)
__device__ __half g_kh[16384 * 64];                     // K: single fp16
__device__ __half g_qh[16384 * 64];                     // Q: single fp16 (pre-scaled)
__device__ __half g_vh[16384 * 64];                     // V: single fp16

// ======================= helpers =======================
DI uint32_t smem_u32(const void* p) {
    uint32_t a;
    asm("{ .reg .u64 t; cvta.to.shared.u64 t, %1; cvt.u32.u64 %0, t; }" : "=r"(a) : "l"(p));
    return a;
}
DI uint32_t sw(uint32_t o) { return o ^ ((o >> 3) & 0x70); }  // SW128 swizzle

// fp16 hi/lo split: hi = rn(a), lo = rn(a - hi)
DI void splith2(float a, float b, uint32_t& h, uint32_t& l) {
    __half ha = __float2half_rn(a), hb = __float2half_rn(b);
    float ra = a - __half2float(ha);
    float rb = b - __half2float(hb);
    h = ((uint32_t)__half_as_ushort(hb) << 16) | (uint32_t)__half_as_ushort(ha);
    asm("cvt.rn.f16x2.f32 %0, %1, %2;" : "=r"(l) : "f"(rb), "f"(ra));
}
DI uint32_t packh(float a, float b) {   // a -> low half, b -> high half (fp16x2)
    uint32_t r;
    asm("cvt.rn.f16x2.f32 %0, %1, %2;" : "=r"(r) : "f"(b), "f"(a));
    return r;
}

DI void mma16816h(float* d, const uint32_t* a, const uint32_t* b) {
    asm volatile(
        "mma.sync.aligned.m16n8k16.row.col.f32.f16.f16.f32 "
        "{%0,%1,%2,%3}, {%4,%5,%6,%7}, {%8,%9}, {%0,%1,%2,%3};"
        : "+f"(d[0]), "+f"(d[1]), "+f"(d[2]), "+f"(d[3])
        : "r"(a[0]), "r"(a[1]), "r"(a[2]), "r"(a[3]), "r"(b[0]), "r"(b[1]));
}
DI void ldsm4(uint32_t* r, uint32_t addr) {
    asm volatile("ldmatrix.sync.aligned.m8n8.x4.shared.b16 {%0,%1,%2,%3}, [%4];"
                 : "=r"(r[0]), "=r"(r[1]), "=r"(r[2]), "=r"(r[3]) : "r"(addr));
}
DI void ldsm4t(uint32_t* r, uint32_t addr) {
    asm volatile("ldmatrix.sync.aligned.m8n8.x4.trans.shared.b16 {%0,%1,%2,%3}, [%4];"
                 : "=r"(r[0]), "=r"(r[1]), "=r"(r[2]), "=r"(r[3]) : "r"(addr));
}
DI void cpa(uint32_t dst, const void* src) {
    asm volatile("cp.async.cg.shared.global [%0], [%1], 16;" :: "r"(dst), "l"(src));
}
#define CP_COMMIT()  asm volatile("cp.async.commit_group;" ::: "memory")
#define CP_WAIT(n)   asm volatile("cp.async.wait_group %0;" :: "n"(n) : "memory")

// ======================= kernel 1: W split to fp16 hi/lo =======================
__global__ void wsplit_kernel(const float* __restrict__ Wk,
                              const float* __restrict__ Wq,
                              const float* __restrict__ Wv) {
    const int idx = blockIdx.x * 256 + threadIdx.x;   // 49152 float4s
    int r = idx >> 8;
    const float* src = (r < 64) ? Wk : (r < 128) ? Wq : Wv;
    float sc = (r >= 64 && r < 128) ? 0.125f : 1.0f;  // fold 1/sqrt(64) into Q
    float4 f = ((const float4*)(src + (size_t)(r & 63) * 1024))[idx & 255];
    uint2 h, l;
    splith2(f.x * sc, f.y * sc, h.x, l.x);
    splith2(f.z * sc, f.w * sc, h.y, l.y);
    ((uint2*)g_wh)[idx] = h;
    ((uint2*)g_wl)[idx] = l;
}

// ======================= kernel 2: projection (x fp16, 2-term) ==============
// out[m][n] = sum_k x[m][k]*Wcat[n][k]; x single fp16, W fp16 hi/lo.
#define PJ_BUF 57344
#define PJ_XS  0
#define PJ_WH  32768
#define PJ_WL  45056
#define PJ_SMEM (2 * PJ_BUF)

__global__ __launch_bounds__(256, 2)
void proj_kernel(const float* __restrict__ x) {
    extern __shared__ char smem[];
    const uint32_t sbase = smem_u32(smem);
    const int tid = threadIdx.x;
    const int wid = tid >> 5, lane = tid & 31;
    const int wm = wid >> 1, wn = wid & 1;
    const int g = lane >> 2, c = lane & 3;
    const int m0 = blockIdx.x * 128;
    const int n0 = blockIdx.y * 96;

    auto load_step = [&](int s, int buf) {
        const int k0 = s * 64;
        const uint32_t bb = sbase + buf * PJ_BUF;
        #pragma unroll
        for (int j = 0; j < 8; ++j) {
            int ch = tid + 256 * j;
            int row = ch >> 4, c16 = ch & 15;
            uint32_t d = (uint32_t)row * 256 +
                         ((((uint32_t)(c16 >> 1) ^ ((uint32_t)row & 7)) * 8 + (c16 & 1) * 4) * 4);
            cpa(bb + PJ_XS + d, x + (size_t)(m0 + row) * 1024 + k0 + c16 * 4);
        }
        #pragma unroll
        for (int j = 0; j < 3; ++j) {
            int ch = tid + 256 * j;
            int row = ch >> 3, col16 = ch & 7;
            uint32_t d = sw((uint32_t)row * 128 + col16 * 16);
            size_t srcoff = (size_t)(n0 + row) * 1024 + k0 + col16 * 8;
            cpa(bb + PJ_WH + d, g_wh + srcoff);
            cpa(bb + PJ_WL + d, g_wl + srcoff);
        }
    };

    float acc[2][6][4];
    #pragma unroll
    for (int t = 0; t < 2; ++t)
        #pragma unroll
        for (int j = 0; j < 6; ++j)
            #pragma unroll
            for (int q = 0; q < 4; ++q) acc[t][j][q] = 0.0f;

    load_step(0, 0);
    CP_COMMIT();

    const uint32_t brow_in = (uint32_t)(((lane >> 4) & 1) * 8 + (lane & 7));
    const uint32_t bcolsel = ((lane >> 3) & 1) * 16;
    const uint32_t arow_lo = (uint32_t)(wm * 32 + (lane >> 2));
    const uint32_t acol_in = (uint32_t)((lane & 3) * 2);

    for (int s = 0; s < 16; ++s) {
        const int buf = s & 1;
        if (s < 15) { load_step(s + 1, buf ^ 1); CP_COMMIT(); CP_WAIT(1); }
        else        { CP_WAIT(0); }
        __syncthreads();

        const char* XS = smem + buf * PJ_BUF + PJ_XS;
        const uint32_t bb = sbase + buf * PJ_BUF;

        #pragma unroll
        for (int kb = 0; kb < 4; ++kb) {
            uint32_t ah[2][4];
            #pragma unroll
            for (int t = 0; t < 2; ++t) {
                const uint32_t r = arow_lo + t * 16;
                const uint32_t x7 = r & 7;
                const uint32_t rb0 = r * 256, rb8 = (r + 8) * 256;
                const uint32_t g0 = (((uint32_t)(kb * 2)     ^ x7) * 8 + acol_in) * 4;
                const uint32_t g1 = (((uint32_t)(kb * 2 + 1) ^ x7) * 8 + acol_in) * 4;
                float2 p0 = *(const float2*)(XS + rb0 + g0);
                float2 p1 = *(const float2*)(XS + rb8 + g0);
                float2 p2 = *(const float2*)(XS + rb0 + g1);
                float2 p3 = *(const float2*)(XS + rb8 + g1);
                ah[t][0] = packh(p0.x, p0.y);
                ah[t][1] = packh(p1.x, p1.y);
                ah[t][2] = packh(p2.x, p2.y);
                ah[t][3] = packh(p3.x, p3.y);
            }
            #pragma unroll
            for (int nb2 = 0; nb2 < 3; ++nb2) {
                uint32_t bh[4], bl[4];
                uint32_t row = (uint32_t)(wn * 48 + nb2 * 16) + brow_in;
                uint32_t off = sw(row * 128 + kb * 32 + bcolsel);
                ldsm4(bh, bb + PJ_WH + off);
                ldsm4(bl, bb + PJ_WL + off);
                #pragma unroll
                for (int t = 0; t < 2; ++t) {
                    mma16816h(acc[t][2 * nb2],     ah[t], bh);
                    mma16816h(acc[t][2 * nb2],     ah[t], bl);
                    mma16816h(acc[t][2 * nb2 + 1], ah[t], bh + 2);
                    mma16816h(acc[t][2 * nb2 + 1], ah[t], bl + 2);
                }
            }
        }
        __syncthreads();
    }

    // epilogue: K, Q, V -> single fp16 packed pairs
    uint32_t* kh32 = (uint32_t*)g_kh;
    uint32_t* qh32 = (uint32_t*)g_qh;
    uint32_t* vh32 = (uint32_t*)g_vh;
    #pragma unroll
    for (int t = 0; t < 2; ++t) {
        const int r0 = m0 + wm * 32 + t * 16 + g;
        #pragma unroll
        for (int j = 0; j < 6; ++j) {
            const int ncol = n0 + wn * 48 + j * 8 + 2 * c;
            uint32_t* dh;
            int c2;
            if (ncol < 64)       { dh = kh32; c2 = ncol >> 1; }
            else if (ncol < 128) { dh = qh32; c2 = (ncol - 64) >> 1; }
            else                 { dh = vh32; c2 = (ncol - 128) >> 1; }
            dh[(size_t)r0 * 32 + c2]       = packh(acc[t][j][0], acc[t][j][1]);
            dh[(size_t)(r0 + 8) * 32 + c2] = packh(acc[t][j][2], acc[t][j][3]);
        }
    }
}

// ======================= kernel 3: attention (all single fp16) ==============
// S = Q K^T: 1 MMA/n8-block; PV: 1 MMA/n8-block. 64 MMAs/tile.
#define AT_BUF 16384
#define AT_KH  0
#define AT_VH  8192
#define AT_SMEM (2 * AT_BUF)

__global__ __launch_bounds__(128, 2)
void attn_kernel(float* __restrict__ out) {
    extern __shared__ char smem[];
    const uint32_t sbase = smem_u32(smem);
    const int tid = threadIdx.x;
    const int wid = tid >> 5, lane = tid & 31;
    const int g = lane >> 2, c = lane & 3;
    const int b = blockIdx.y;
    const int q0 = blockIdx.x * 64;

    // ---- Q fragments in registers (single fp16) ----
    uint32_t qh[4][4];
    {
        const uint32_t* qh32 = (const uint32_t*)g_qh;
        const size_t r0 = (size_t)(b * 2048 + q0 + wid * 16 + g) * 32;
        const size_t r1 = r0 + 8 * 32;
        #pragma unroll
        for (int kb = 0; kb < 4; ++kb) {
            const int c0 = kb * 8 + c;
            qh[kb][0] = qh32[r0 + c0];     qh[kb][1] = qh32[r1 + c0];
            qh[kb][2] = qh32[r0 + c0 + 4]; qh[kb][3] = qh32[r1 + c0 + 4];
        }
    }

    auto load_kv = [&](int kt, int buf) {
        const uint32_t bb = sbase + buf * AT_BUF;
        #pragma unroll
        for (int j = 0; j < 4; ++j) {
            int ch = tid + 128 * j;
            int row = ch >> 3, col16 = ch & 7;
            uint32_t d = sw((uint32_t)row * 128 + col16 * 16);
            size_t srcoff = (size_t)(b * 2048 + kt * 64 + row) * 64 + col16 * 8;
            cpa(bb + AT_KH + d, g_kh + srcoff);
            cpa(bb + AT_VH + d, g_vh + srcoff);
        }
    };

    float o[8][4];
    #pragma unroll
    for (int f = 0; f < 8; ++f)
        #pragma unroll
        for (int q = 0; q < 4; ++q) o[f][q] = 0.0f;
    float l0 = 0.0f, l1 = 0.0f;

    load_kv(0, 0);
    CP_COMMIT();

    const uint32_t kb_row_in = (uint32_t)(((lane >> 4) & 1) * 8 + (lane & 7));
    const uint32_t kb_colsel = ((lane >> 3) & 1) * 16;
    const uint32_t vb_row_in = (uint32_t)(((lane >> 3) & 1) * 8 + (lane & 7));

    for (int kt = 0; kt < 32; ++kt) {
        const int buf = kt & 1;
        if (kt < 31) { load_kv(kt + 1, buf ^ 1); CP_COMMIT(); CP_WAIT(1); }
        else         { CP_WAIT(0); }
        __syncthreads();
        const uint32_t bb = sbase + buf * AT_BUF;

        // ---- S = Q K^T (single fp16 term) ----
        float s[8][4];
        #pragma unroll
        for (int f = 0; f < 8; ++f)
            #pragma unroll
            for (int q = 0; q < 4; ++q) s[f][q] = 0.0f;

        #pragma unroll
        for (int kb = 0; kb < 4; ++kb) {
            #pragma unroll
            for (int nb2 = 0; nb2 < 4; ++nb2) {
                uint32_t bh[4];
                uint32_t row = (uint32_t)(nb2 * 16) + kb_row_in;
                uint32_t off = sw(row * 128 + kb * 32 + kb_colsel);
                ldsm4(bh, bb + AT_KH + off);
                mma16816h(s[2 * nb2],     qh[kb], bh);
                mma16816h(s[2 * nb2 + 1], qh[kb], bh + 2);
            }
        }

        // ---- per-kb fused: exp(kb) -> PV(kb); single fp16 P, V ----
        #pragma unroll
        for (int kb = 0; kb < 4; ++kb) {
            uint32_t ph[4];
            #pragma unroll
            for (int fo = 0; fo < 2; ++fo) {
                const int f = 2 * kb + fo;
                float p0 = __expf(s[f][0]), p1 = __expf(s[f][1]);
                float p2 = __expf(s[f][2]), p3 = __expf(s[f][3]);
                l0 += p0 + p1;
                l1 += p2 + p3;
                ph[2 * fo]     = packh(p0, p1);
                ph[2 * fo + 1] = packh(p2, p3);
            }
            #pragma unroll
            for (int nb2 = 0; nb2 < 4; ++nb2) {
                uint32_t vhf[4];
                uint32_t row = (uint32_t)(kb * 16) + vb_row_in;
                uint32_t off = sw(row * 128 + (2 * nb2 + (lane >> 4)) * 16);
                ldsm4t(vhf, bb + AT_VH + off);
                mma16816h(o[2 * nb2],     ph, vhf);
                mma16816h(o[2 * nb2 + 1], ph, vhf + 2);
            }
        }
        __syncthreads();
    }

    // ---- epilogue ----
    l0 += __shfl_xor_sync(0xffffffffu, l0, 1);
    l0 += __shfl_xor_sync(0xffffffffu, l0, 2);
    l1 += __shfl_xor_sync(0xffffffffu, l1, 1);
    l1 += __shfl_xor_sync(0xffffffffu, l1, 2);
    const float inv0 = 1.0f / l0, inv1 = 1.0f / l1;

    const int r0 = b * 2048 + q0 + wid * 16 + g;
    #pragma unroll
    for (int f = 0; f < 8; ++f) {
        const int col = f * 8 + 2 * c;
        float2 v0 = make_float2(o[f][0] * inv0, o[f][1] * inv0);
        float2 v1 = make_float2(o[f][2] * inv1, o[f][3] * inv1);
        *(float2*)(out + (size_t)r0 * 64 + col)       = v0;
        *(float2*)(out + (size_t)(r0 + 8) * 64 + col) = v1;
    }
}

// ======================= launch =======================
extern "C" void kernel_launch(void* const* d_in, const int* in_sizes, int n_in,
                              void* d_out, int out_size) {
    const float* x  = (const float*)d_in[0];
    const float* Wk = (const float*)d_in[1];
    const float* Wq = (const float*)d_in[2];
    const float* Wv = (const float*)d_in[3];
    float* out = (float*)d_out;

    cudaFuncSetAttribute(proj_kernel, cudaFuncAttributeMaxDynamicSharedMemorySize, PJ_SMEM);
    cudaFuncSetAttribute(attn_kernel, cudaFuncAttributeMaxDynamicSharedMemorySize, AT_SMEM);

    wsplit_kernel<<<192, 256>>>(Wk, Wq, Wv);
    proj_kernel<<<dim3(128, 2), 256, PJ_SMEM>>>(x);
    attn_kernel<<<dim3(32, 8), 128, AT_SMEM>>>(out);
}

// round 17
// speedup vs baseline: 2.4148x; 1.2517x over previous
#include <cuda_runtime.h>
#include <cuda_bf16.h>
#include <cuda_fp16.h>
#include <cstdint>

#define DI __device__ __forceinline__

// ======================= scratch (all single fp16) =======================
__device__ __half g_wh[192 * 1024];     // W: single fp16
__device__ __half g_kh[16384 * 64];     // K: single fp16
__device__ __half g_qh[16384 * 64];     // Q: single fp16 (pre-scaled by 0.125)
__device__ __half g_vh[16384 * 64];     // V: single fp16

// ======================= helpers =======================
DI uint32_t smem_u32(const void* p) {
    uint32_t a;
    asm("{ .reg .u64 t; cvta.to.shared.u64 t, %1; cvt.u32.u64 %0, t; }" : "=r"(a) : "l"(p));
    return a;
}
DI uint32_t sw(uint32_t o) { return o ^ ((o >> 3) & 0x70); }  // SW128 swizzle

DI uint32_t packh(float a, float b) {   // a -> low half, b -> high half (fp16x2)
    uint32_t r;
    asm("cvt.rn.f16x2.f32 %0, %1, %2;" : "=r"(r) : "f"(b), "f"(a));
    return r;
}

DI void mma16816h(float* d, const uint32_t* a, const uint32_t* b) {
    asm volatile(
        "mma.sync.aligned.m16n8k16.row.col.f32.f16.f16.f32 "
        "{%0,%1,%2,%3}, {%4,%5,%6,%7}, {%8,%9}, {%0,%1,%2,%3};"
        : "+f"(d[0]), "+f"(d[1]), "+f"(d[2]), "+f"(d[3])
        : "r"(a[0]), "r"(a[1]), "r"(a[2]), "r"(a[3]), "r"(b[0]), "r"(b[1]));
}
DI void ldsm4(uint32_t* r, uint32_t addr) {
    asm volatile("ldmatrix.sync.aligned.m8n8.x4.shared.b16 {%0,%1,%2,%3}, [%4];"
                 : "=r"(r[0]), "=r"(r[1]), "=r"(r[2]), "=r"(r[3]) : "r"(addr));
}
DI void ldsm4t(uint32_t* r, uint32_t addr) {
    asm volatile("ldmatrix.sync.aligned.m8n8.x4.trans.shared.b16 {%0,%1,%2,%3}, [%4];"
                 : "=r"(r[0]), "=r"(r[1]), "=r"(r[2]), "=r"(r[3]) : "r"(addr));
}
DI void cpa(uint32_t dst, const void* src) {
    asm volatile("cp.async.cg.shared.global [%0], [%1], 16;" :: "r"(dst), "l"(src));
}
#define CP_COMMIT()  asm volatile("cp.async.commit_group;" ::: "memory")
#define CP_WAIT(n)   asm volatile("cp.async.wait_group %0;" :: "n"(n) : "memory")

// ======================= kernel 1: W convert to fp16 =======================
__global__ void wsplit_kernel(const float* __restrict__ Wk,
                              const float* __restrict__ Wq,
                              const float* __restrict__ Wv) {
    const int idx = blockIdx.x * 256 + threadIdx.x;   // 49152 float4s
    int r = idx >> 8;
    const float* src = (r < 64) ? Wk : (r < 128) ? Wq : Wv;
    float sc = (r >= 64 && r < 128) ? 0.125f : 1.0f;  // fold 1/sqrt(64) into Q
    float4 f = ((const float4*)(src + (size_t)(r & 63) * 1024))[idx & 255];
    uint2 h;
    h.x = packh(f.x * sc, f.y * sc);
    h.y = packh(f.z * sc, f.w * sc);
    ((uint2*)g_wh)[idx] = h;
}

// ======================= kernel 2: projection (pure fp16, 1 term) ===========
// out[m][n] = sum_k x[m][k]*Wcat[n][k]; x cvt to fp16 in regs, W single fp16.
#define PJ_BUF 45056
#define PJ_XS  0
#define PJ_WH  32768
#define PJ_SMEM (2 * PJ_BUF)

__global__ __launch_bounds__(256, 2)
void proj_kernel(const float* __restrict__ x) {
    extern __shared__ char smem[];
    const uint32_t sbase = smem_u32(smem);
    const int tid = threadIdx.x;
    const int wid = tid >> 5, lane = tid & 31;
    const int wm = wid >> 1, wn = wid & 1;
    const int g = lane >> 2, c = lane & 3;
    const int m0 = blockIdx.x * 128;
    const int n0 = blockIdx.y * 96;

    auto load_step = [&](int s, int buf) {
        const int k0 = s * 64;
        const uint32_t bb = sbase + buf * PJ_BUF;
        #pragma unroll
        for (int j = 0; j < 8; ++j) {
            int ch = tid + 256 * j;
            int row = ch >> 4, c16 = ch & 15;
            uint32_t d = (uint32_t)row * 256 +
                         ((((uint32_t)(c16 >> 1) ^ ((uint32_t)row & 7)) * 8 + (c16 & 1) * 4) * 4);
            cpa(bb + PJ_XS + d, x + (size_t)(m0 + row) * 1024 + k0 + c16 * 4);
        }
        #pragma unroll
        for (int j = 0; j < 3; ++j) {
            int ch = tid + 256 * j;
            int row = ch >> 3, col16 = ch & 7;
            uint32_t d = sw((uint32_t)row * 128 + col16 * 16);
            size_t srcoff = (size_t)(n0 + row) * 1024 + k0 + col16 * 8;
            cpa(bb + PJ_WH + d, g_wh + srcoff);
        }
    };

    float acc[2][6][4];
    #pragma unroll
    for (int t = 0; t < 2; ++t)
        #pragma unroll
        for (int j = 0; j < 6; ++j)
            #pragma unroll
            for (int q = 0; q < 4; ++q) acc[t][j][q] = 0.0f;

    load_step(0, 0);
    CP_COMMIT();

    const uint32_t brow_in = (uint32_t)(((lane >> 4) & 1) * 8 + (lane & 7));
    const uint32_t bcolsel = ((lane >> 3) & 1) * 16;
    const uint32_t arow_lo = (uint32_t)(wm * 32 + (lane >> 2));
    const uint32_t acol_in = (uint32_t)((lane & 3) * 2);

    for (int s = 0; s < 16; ++s) {
        const int buf = s & 1;
        if (s < 15) { load_step(s + 1, buf ^ 1); CP_COMMIT(); CP_WAIT(1); }
        else        { CP_WAIT(0); }
        __syncthreads();

        const char* XS = smem + buf * PJ_BUF + PJ_XS;
        const uint32_t bb = sbase + buf * PJ_BUF;

        #pragma unroll
        for (int kb = 0; kb < 4; ++kb) {
            uint32_t ah[2][4];
            #pragma unroll
            for (int t = 0; t < 2; ++t) {
                const uint32_t r = arow_lo + t * 16;
                const uint32_t x7 = r & 7;
                const uint32_t rb0 = r * 256, rb8 = (r + 8) * 256;
                const uint32_t g0 = (((uint32_t)(kb * 2)     ^ x7) * 8 + acol_in) * 4;
                const uint32_t g1 = (((uint32_t)(kb * 2 + 1) ^ x7) * 8 + acol_in) * 4;
                float2 p0 = *(const float2*)(XS + rb0 + g0);
                float2 p1 = *(const float2*)(XS + rb8 + g0);
                float2 p2 = *(const float2*)(XS + rb0 + g1);
                float2 p3 = *(const float2*)(XS + rb8 + g1);
                ah[t][0] = packh(p0.x, p0.y);
                ah[t][1] = packh(p1.x, p1.y);
                ah[t][2] = packh(p2.x, p2.y);
                ah[t][3] = packh(p3.x, p3.y);
            }
            #pragma unroll
            for (int nb2 = 0; nb2 < 3; ++nb2) {
                uint32_t bh[4];
                uint32_t row = (uint32_t)(wn * 48 + nb2 * 16) + brow_in;
                uint32_t off = sw(row * 128 + kb * 32 + bcolsel);
                ldsm4(bh, bb + PJ_WH + off);
                #pragma unroll
                for (int t = 0; t < 2; ++t) {
                    mma16816h(acc[t][2 * nb2],     ah[t], bh);
                    mma16816h(acc[t][2 * nb2 + 1], ah[t], bh + 2);
                }
            }
        }
        __syncthreads();
    }

    // epilogue: K, Q, V -> single fp16 packed pairs
    uint32_t* kh32 = (uint32_t*)g_kh;
    uint32_t* qh32 = (uint32_t*)g_qh;
    uint32_t* vh32 = (uint32_t*)g_vh;
    #pragma unroll
    for (int t = 0; t < 2; ++t) {
        const int r0 = m0 + wm * 32 + t * 16 + g;
        #pragma unroll
        for (int j = 0; j < 6; ++j) {
            const int ncol = n0 + wn * 48 + j * 8 + 2 * c;
            uint32_t* dh;
            int c2;
            if (ncol < 64)       { dh = kh32; c2 = ncol >> 1; }
            else if (ncol < 128) { dh = qh32; c2 = (ncol - 64) >> 1; }
            else                 { dh = vh32; c2 = (ncol - 128) >> 1; }
            dh[(size_t)r0 * 32 + c2]       = packh(acc[t][j][0], acc[t][j][1]);
            dh[(size_t)(r0 + 8) * 32 + c2] = packh(acc[t][j][2], acc[t][j][3]);
        }
    }
}

// ======================= kernel 3: attention (all single fp16, R16) =========
#define AT_BUF 16384
#define AT_KH  0
#define AT_VH  8192
#define AT_SMEM (2 * AT_BUF)

__global__ __launch_bounds__(128, 2)
void attn_kernel(float* __restrict__ out) {
    extern __shared__ char smem[];
    const uint32_t sbase = smem_u32(smem);
    const int tid = threadIdx.x;
    const int wid = tid >> 5, lane = tid & 31;
    const int g = lane >> 2, c = lane & 3;
    const int b = blockIdx.y;
    const int q0 = blockIdx.x * 64;

    // ---- Q fragments in registers (single fp16) ----
    uint32_t qh[4][4];
    {
        const uint32_t* qh32 = (const uint32_t*)g_qh;
        const size_t r0 = (size_t)(b * 2048 + q0 + wid * 16 + g) * 32;
        const size_t r1 = r0 + 8 * 32;
        #pragma unroll
        for (int kb = 0; kb < 4; ++kb) {
            const int c0 = kb * 8 + c;
            qh[kb][0] = qh32[r0 + c0];     qh[kb][1] = qh32[r1 + c0];
            qh[kb][2] = qh32[r0 + c0 + 4]; qh[kb][3] = qh32[r1 + c0 + 4];
        }
    }

    auto load_kv = [&](int kt, int buf) {
        const uint32_t bb = sbase + buf * AT_BUF;
        #pragma unroll
        for (int j = 0; j < 4; ++j) {
            int ch = tid + 128 * j;
            int row = ch >> 3, col16 = ch & 7;
            uint32_t d = sw((uint32_t)row * 128 + col16 * 16);
            size_t srcoff = (size_t)(b * 2048 + kt * 64 + row) * 64 + col16 * 8;
            cpa(bb + AT_KH + d, g_kh + srcoff);
            cpa(bb + AT_VH + d, g_vh + srcoff);
        }
    };

    float o[8][4];
    #pragma unroll
    for (int f = 0; f < 8; ++f)
        #pragma unroll
        for (int q = 0; q < 4; ++q) o[f][q] = 0.0f;
    float l0 = 0.0f, l1 = 0.0f;

    load_kv(0, 0);
    CP_COMMIT();

    const uint32_t kb_row_in = (uint32_t)(((lane >> 4) & 1) * 8 + (lane & 7));
    const uint32_t kb_colsel = ((lane >> 3) & 1) * 16;
    const uint32_t vb_row_in = (uint32_t)(((lane >> 3) & 1) * 8 + (lane & 7));

    for (int kt = 0; kt < 32; ++kt) {
        const int buf = kt & 1;
        if (kt < 31) { load_kv(kt + 1, buf ^ 1); CP_COMMIT(); CP_WAIT(1); }
        else         { CP_WAIT(0); }
        __syncthreads();
        const uint32_t bb = sbase + buf * AT_BUF;

        // ---- S = Q K^T (single fp16 term) ----
        float s[8][4];
        #pragma unroll
        for (int f = 0; f < 8; ++f)
            #pragma unroll
            for (int q = 0; q < 4; ++q) s[f][q] = 0.0f;

        #pragma unroll
        for (int kb = 0; kb < 4; ++kb) {
            #pragma unroll
            for (int nb2 = 0; nb2 < 4; ++nb2) {
                uint32_t bh[4];
                uint32_t row = (uint32_t)(nb2 * 16) + kb_row_in;
                uint32_t off = sw(row * 128 + kb * 32 + kb_colsel);
                ldsm4(bh, bb + AT_KH + off);
                mma16816h(s[2 * nb2],     qh[kb], bh);
                mma16816h(s[2 * nb2 + 1], qh[kb], bh + 2);
            }
        }

        // ---- per-kb fused: exp(kb) -> PV(kb); single fp16 P, V ----
        #pragma unroll
        for (int kb = 0; kb < 4; ++kb) {
            uint32_t ph[4];
            #pragma unroll
            for (int fo = 0; fo < 2; ++fo) {
                const int f = 2 * kb + fo;
                float p0 = __expf(s[f][0]), p1 = __expf(s[f][1]);
                float p2 = __expf(s[f][2]), p3 = __expf(s[f][3]);
                l0 += p0 + p1;
                l1 += p2 + p3;
                ph[2 * fo]     = packh(p0, p1);
                ph[2 * fo + 1] = packh(p2, p3);
            }
            #pragma unroll
            for (int nb2 = 0; nb2 < 4; ++nb2) {
                uint32_t vhf[4];
                uint32_t row = (uint32_t)(kb * 16) + vb_row_in;
                uint32_t off = sw(row * 128 + (2 * nb2 + (lane >> 4)) * 16);
                ldsm4t(vhf, bb + AT_VH + off);
                mma16816h(o[2 * nb2],     ph, vhf);
                mma16816h(o[2 * nb2 + 1], ph, vhf + 2);
            }
        }
        __syncthreads();
    }

    // ---- epilogue ----
    l0 += __shfl_xor_sync(0xffffffffu, l0, 1);
    l0 += __shfl_xor_sync(0xffffffffu, l0, 2);
    l1 += __shfl_xor_sync(0xffffffffu, l1, 1);
    l1 += __shfl_xor_sync(0xffffffffu, l1, 2);
    const float inv0 = 1.0f / l0, inv1 = 1.0f / l1;

    const int r0 = b * 2048 + q0 + wid * 16 + g;
    #pragma unroll
    for (int f = 0; f < 8; ++f) {
        const int col = f * 8 + 2 * c;
        float2 v0 = make_float2(o[f][0] * inv0, o[f][1] * inv0);
        float2 v1 = make_float2(o[f][2] * inv1, o[f][3] * inv1);
        *(float2*)(out + (size_t)r0 * 64 + col)       = v0;
        *(float2*)(out + (size_t)(r0 + 8) * 64 + col) = v1;
    }
}

// ======================= launch =======================
extern "C" void kernel_launch(void* const* d_in, const int* in_sizes, int n_in,
                              void* d_out, int out_size) {
    const float* x  = (const float*)d_in[0];
    const float* Wk = (const float*)d_in[1];
    const float* Wq = (const float*)d_in[2];
    const float* Wv = (const float*)d_in[3];
    float* out = (float*)d_out;

    cudaFuncSetAttribute(proj_kernel, cudaFuncAttributeMaxDynamicSharedMemorySize, PJ_SMEM);
    cudaFuncSetAttribute(attn_kernel, cudaFuncAttributeMaxDynamicSharedMemorySize, AT_SMEM);

    wsplit_kernel<<<192, 256>>>(Wk, Wq, Wv);
    proj_kernel<<<dim3(128, 2), 256, PJ_SMEM>>>(x);
    attn_kernel<<<dim3(32, 8), 128, AT_SMEM>>>(out);
}